// round 1
// baseline (speedup 1.0000x reference)
#include <cuda_runtime.h>
#include <math.h>

// ---------------- static problem config ----------------
#define NQ     13294
#define BATCH  2
#define MROWS  (BATCH * NQ)     // 26588
#define E_     256
#define F_     1024
#define NHEAD  8
#define HDIM   32
#define NLVL   4
#define NPNT   4
#define EPS    1e-5f

// ---------------- scratch (static device globals; no allocation) ----------------
__device__ float g_x   [MROWS * E_];   // running activation
__device__ float g_v   [MROWS * E_];   // value projection
__device__ float g_off [MROWS * E_];   // sampling offsets (NH*L*P*2 = 256)
__device__ float g_awl [MROWS * 128];  // attention-weight logits -> softmaxed in place
__device__ float g_samp[MROWS * E_];   // deformable-attn sampled output
__device__ float g_tmp [MROWS * E_];   // post-Wo / post-Wf2 buffer
__device__ float g_ffn [MROWS * F_];   // FFN hidden

__constant__ int c_w[NLVL]     = {100, 50, 25, 13};
__constant__ int c_h[NLVL]     = {100, 50, 25, 13};
__constant__ int c_start[NLVL] = {0, 10000, 12500, 13125};

// ---------------- utility: copy ----------------
__global__ void copy_kernel(const float* __restrict__ src, float* __restrict__ dst, int n) {
    int i = blockIdx.x * blockDim.x + threadIdx.x;
    if (i < n) dst[i] = src[i];
}

// ---------------- SGEMM: C = act(A[MxK] * W[KxN] + bias) ----------------
// 64x64 block tile, BK=16, 256 threads, 4x4 per-thread tile, float4 IO.
#define BM 64
#define BN_ 64
#define BK 16

__global__ __launch_bounds__(256) void sgemm_bias(
    const float* __restrict__ A, const float* __restrict__ W,
    const float* __restrict__ bias, float* __restrict__ C,
    int M, int K, int Nc, int relu)
{
    __shared__ float As[BK][BM];
    __shared__ float Bs[BK][BN_];

    const int tid = threadIdx.x;
    const int block_m = blockIdx.y * BM;
    const int block_n = blockIdx.x * BN_;

    const int a_row  = tid >> 2;          // 0..63
    const int a_col4 = (tid & 3) << 2;    // 0,4,8,12
    const int b_row  = tid >> 4;          // 0..15
    const int b_col4 = (tid & 15) << 2;   // 0..60

    const int tx = tid & 15;              // n-direction
    const int ty = tid >> 4;              // m-direction

    float acc[4][4] = {};

    for (int k0 = 0; k0 < K; k0 += BK) {
        // load A tile (guard M), store transposed As[k][m]
        float4 av = make_float4(0.f, 0.f, 0.f, 0.f);
        int gr = block_m + a_row;
        if (gr < M) av = *(const float4*)(A + (size_t)gr * K + k0 + a_col4);
        As[a_col4 + 0][a_row] = av.x;
        As[a_col4 + 1][a_row] = av.y;
        As[a_col4 + 2][a_row] = av.z;
        As[a_col4 + 3][a_row] = av.w;

        // load B tile (N always multiple of 64, K multiple of 16)
        float4 bv4 = *(const float4*)(W + (size_t)(k0 + b_row) * Nc + block_n + b_col4);
        *(float4*)&Bs[b_row][b_col4] = bv4;

        __syncthreads();

        #pragma unroll
        for (int kk = 0; kk < BK; kk++) {
            float4 a4 = *(const float4*)&As[kk][ty * 4];
            float4 b4 = *(const float4*)&Bs[kk][tx * 4];
            float a[4] = {a4.x, a4.y, a4.z, a4.w};
            float b[4] = {b4.x, b4.y, b4.z, b4.w};
            #pragma unroll
            for (int i = 0; i < 4; i++)
                #pragma unroll
                for (int j = 0; j < 4; j++)
                    acc[i][j] += a[i] * b[j];
        }
        __syncthreads();
    }

    #pragma unroll
    for (int i = 0; i < 4; i++) {
        int r = block_m + ty * 4 + i;
        if (r >= M) continue;
        #pragma unroll
        for (int j = 0; j < 4; j++) {
            int cidx = block_n + tx * 4 + j;
            float val = acc[i][j] + bias[cidx];
            if (relu) val = fmaxf(val, 0.f);
            C[(size_t)r * Nc + cidx] = val;
        }
    }
}

// ---------------- softmax over 16 (per query-head), in place ----------------
__global__ void softmax16_kernel(float* __restrict__ a, int total) {
    int i = blockIdx.x * blockDim.x + threadIdx.x;   // i = bn*8 + h
    if (i >= total) return;
    float* p = a + (size_t)(i >> 3) * 128 + (i & 7) * 16;
    float v[16], mx = -1e30f;
    #pragma unroll
    for (int k = 0; k < 16; k++) { v[k] = p[k]; mx = fmaxf(mx, v[k]); }
    float s = 0.f;
    #pragma unroll
    for (int k = 0; k < 16; k++) { v[k] = __expf(v[k] - mx); s += v[k]; }
    float inv = 1.f / s;
    #pragma unroll
    for (int k = 0; k < 16; k++) p[k] = v[k] * inv;
}

// ---------------- multi-scale deformable attention sampling ----------------
// one warp per (bn, head); lane = channel within head (HDIM=32)
__global__ __launch_bounds__(256) void deform_attn_kernel(
    const float* __restrict__ v, const float* __restrict__ off,
    const float* __restrict__ aw, const float* __restrict__ ref,
    float* __restrict__ out)
{
    int gw = blockIdx.x * 8 + (threadIdx.x >> 5);
    if (gw >= MROWS * NHEAD) return;
    int lane = threadIdx.x & 31;
    int h  = gw & 7;
    int bn = gw >> 3;
    int b  = bn / NQ;
    const size_t vb = (size_t)b * NQ;

    const float* offp = off + (size_t)bn * 256 + h * 32;  // (L,P,2)
    const float* awp  = aw  + (size_t)bn * 128 + h * 16;  // (L,P)

    float acc = 0.f;

    #pragma unroll
    for (int lvl = 0; lvl < NLVL; lvl++) {
        const int W = c_w[lvl], H = c_h[lvl], S = c_start[lvl];
        const float fw = (float)W, fh = (float)H;
        float rx = ref[((size_t)bn * NLVL + lvl) * 2 + 0];
        float ry = ref[((size_t)bn * NLVL + lvl) * 2 + 1];

        #pragma unroll
        for (int p = 0; p < NPNT; p++) {
            float ox = offp[(lvl * NPNT + p) * 2 + 0];
            float oy = offp[(lvl * NPNT + p) * 2 + 1];
            float a  = awp[lvl * NPNT + p];

            float locx = rx + ox / fw;    // match reference rounding order
            float locy = ry + oy / fh;
            float xs = locx * fw - 0.5f;
            float ys = locy * fh - 0.5f;

            float fxs = floorf(xs), fys = floorf(ys);
            int x0 = (int)fxs, y0 = (int)fys;
            float lx = xs - fxs, ly = ys - fys;

            float w00 = (1.f - lx) * (1.f - ly) * a;
            float w01 = lx * (1.f - ly) * a;
            float w10 = (1.f - lx) * ly * a;
            float w11 = lx * ly * a;

            int x1 = x0 + 1, y1 = y0 + 1;
            bool vx0 = (x0 >= 0) & (x0 < W);
            bool vx1 = (x1 >= 0) & (x1 < W);
            bool vy0 = (y0 >= 0) & (y0 < H);
            bool vy1 = (y1 >= 0) & (y1 < H);

            if (vy0 & vx0) acc += w00 * v[(vb + S + (size_t)y0 * W + x0) * E_ + h * HDIM + lane];
            if (vy0 & vx1) acc += w01 * v[(vb + S + (size_t)y0 * W + x1) * E_ + h * HDIM + lane];
            if (vy1 & vx0) acc += w10 * v[(vb + S + (size_t)y1 * W + x0) * E_ + h * HDIM + lane];
            if (vy1 & vx1) acc += w11 * v[(vb + S + (size_t)y1 * W + x1) * E_ + h * HDIM + lane];
        }
    }
    out[(size_t)bn * E_ + h * HDIM + lane] = acc;
}

// ---------------- fused residual add + LayerNorm (warp per row) ----------------
__global__ __launch_bounds__(256) void add_ln_kernel(
    const float* __restrict__ x, const float* __restrict__ r,
    const float* __restrict__ gamma, const float* __restrict__ beta,
    float* __restrict__ out, int M)
{
    int row = blockIdx.x * 8 + (threadIdx.x >> 5);
    if (row >= M) return;
    int lane = threadIdx.x & 31;

    const float* xp = x + (size_t)row * E_;
    const float* rp = r + (size_t)row * E_;

    float vals[8];
    float s = 0.f;
    #pragma unroll
    for (int i = 0; i < 8; i++) {
        vals[i] = xp[lane + i * 32] + rp[lane + i * 32];
        s += vals[i];
    }
    #pragma unroll
    for (int o = 16; o > 0; o >>= 1) s += __shfl_xor_sync(0xFFFFFFFFu, s, o);
    float mean = s * (1.f / E_);

    float vs = 0.f;
    #pragma unroll
    for (int i = 0; i < 8; i++) {
        float d = vals[i] - mean;
        vs += d * d;
    }
    #pragma unroll
    for (int o = 16; o > 0; o >>= 1) vs += __shfl_xor_sync(0xFFFFFFFFu, vs, o);
    float inv = rsqrtf(vs * (1.f / E_) + EPS);

    float* op = out + (size_t)row * E_;
    #pragma unroll
    for (int i = 0; i < 8; i++) {
        int c = lane + i * 32;
        op[c] = (vals[i] - mean) * inv * gamma[c] + beta[c];
    }
}

// ---------------- launcher ----------------
static inline void run_gemm(const float* A, const float* W, const float* b,
                            float* C, int M, int K, int Nc, int relu) {
    dim3 grid(Nc / BN_, (M + BM - 1) / BM);
    sgemm_bias<<<grid, 256>>>(A, W, b, C, M, K, Nc, relu);
}

extern "C" void kernel_launch(void* const* d_in, const int* in_sizes, int n_in,
                              void* d_out, int out_size) {
    const float* src  = (const float*)d_in[0];
    const float* ref  = (const float*)d_in[1];
    // d_in[2] spatial_shapes, d_in[3] level_start_index: static, baked in
    const float* Woff = (const float*)d_in[4];
    const float* boff = (const float*)d_in[5];
    const float* Waw  = (const float*)d_in[6];
    const float* baw  = (const float*)d_in[7];
    const float* Wv   = (const float*)d_in[8];
    const float* bv   = (const float*)d_in[9];
    const float* Wo   = (const float*)d_in[10];
    const float* bo   = (const float*)d_in[11];
    const float* ln1g = (const float*)d_in[12];
    const float* ln1b = (const float*)d_in[13];
    const float* Wf1  = (const float*)d_in[14];
    const float* bf1  = (const float*)d_in[15];
    const float* Wf2  = (const float*)d_in[16];
    const float* bf2  = (const float*)d_in[17];
    const float* ln2g = (const float*)d_in[18];
    const float* ln2b = (const float*)d_in[19];
    float* out = (float*)d_out;

    float *px, *pv, *poff, *pawl, *psamp, *ptmp, *pffn;
    cudaGetSymbolAddress((void**)&px,    g_x);
    cudaGetSymbolAddress((void**)&pv,    g_v);
    cudaGetSymbolAddress((void**)&poff,  g_off);
    cudaGetSymbolAddress((void**)&pawl,  g_awl);
    cudaGetSymbolAddress((void**)&psamp, g_samp);
    cudaGetSymbolAddress((void**)&ptmp,  g_tmp);
    cudaGetSymbolAddress((void**)&pffn,  g_ffn);

    const int M = MROWS;
    const int nElem = M * E_;

    copy_kernel<<<(nElem + 255) / 256, 256>>>(src, px, nElem);

    for (int layer = 0; layer < 6; layer++) {
        // projections
        run_gemm(px, Wv,   bv,   pv,   M, E_, E_,  0);   // value
        run_gemm(px, Woff, boff, poff, M, E_, 256, 0);   // offsets (NH*L*P*2)
        run_gemm(px, Waw,  baw,  pawl, M, E_, 128, 0);   // attn-weight logits

        softmax16_kernel<<<(M * NHEAD + 255) / 256, 256>>>(pawl, M * NHEAD);

        deform_attn_kernel<<<M, 256>>>(pv, poff, pawl, ref, psamp);

        run_gemm(psamp, Wo, bo, ptmp, M, E_, E_, 0);     // output projection
        add_ln_kernel<<<(M + 7) / 8, 256>>>(px, ptmp, ln1g, ln1b, px, M);

        // FFN
        run_gemm(px,   Wf1, bf1, pffn, M, E_, F_, 1);    // relu
        run_gemm(pffn, Wf2, bf2, ptmp, M, F_, E_, 0);

        float* dst = (layer == 5) ? out : px;
        add_ln_kernel<<<(M + 7) / 8, 256>>>(px, ptmp, ln2g, ln2b, dst, M);
    }
}

// round 2
// speedup vs baseline: 1.9350x; 1.9350x over previous
#include <cuda_runtime.h>
#include <math.h>
#include <stdint.h>

// ---------------- static problem config ----------------
#define NQ     13294
#define BATCH  2
#define MROWS  (BATCH * NQ)     // 26588
#define E_     256
#define F_     1024
#define NHEAD  8
#define HDIM   32
#define NLVL   4
#define NPNT   4
#define EPS    1e-5f

// ---------------- scratch (static device globals; no allocation) ----------------
__device__ float g_x   [MROWS * E_];
__device__ float g_v   [MROWS * E_];
__device__ float g_off [MROWS * E_];
__device__ float g_awl [MROWS * 128];
__device__ float g_samp[MROWS * E_];
__device__ float g_tmp [MROWS * E_];
__device__ float g_ffn [MROWS * F_];

__constant__ int c_w[NLVL]     = {100, 50, 25, 13};
__constant__ int c_h[NLVL]     = {100, 50, 25, 13};
__constant__ int c_start[NLVL] = {0, 10000, 12500, 13125};

// ---------------- utility: copy ----------------
__global__ void copy_kernel(const float* __restrict__ src, float* __restrict__ dst, int n) {
    int i = blockIdx.x * blockDim.x + threadIdx.x;
    if (i < n) dst[i] = src[i];
}

// ---------------- TF32 tensor-core GEMM ----------------
// C = act(A[MxK] * W[KxN] + bias), 128x128x16 CTA tile, 256 threads (8 warps 2x4),
// warp tile 64x32 via 4x4 mma.m16n8k8, double-buffered smem.
#define TBM 128
#define TBN 128
#define TBK 16
#define APAD 20   // As row stride (floats): conflict-free frag loads, 16B aligned
#define BPAD 136  // Bs row stride

__device__ __forceinline__ float to_tf32(float x) {
    float r;
    asm("cvt.rna.tf32.f32 %0, %1;" : "=f"(r) : "f"(x));
    return r;
}

__device__ __forceinline__ void mma_tf32(
    float& d0, float& d1, float& d2, float& d3,
    uint32_t a0, uint32_t a1, uint32_t a2, uint32_t a3,
    uint32_t b0, uint32_t b1)
{
    asm volatile(
        "mma.sync.aligned.m16n8k8.row.col.f32.tf32.tf32.f32 "
        "{%0,%1,%2,%3}, {%4,%5,%6,%7}, {%8,%9}, {%0,%1,%2,%3};"
        : "+f"(d0), "+f"(d1), "+f"(d2), "+f"(d3)
        : "r"(a0), "r"(a1), "r"(a2), "r"(a3), "r"(b0), "r"(b1));
}

__global__ __launch_bounds__(256, 2) void gemm_tf32(
    const float* __restrict__ A, const float* __restrict__ W,
    const float* __restrict__ bias, float* __restrict__ C,
    int M, int K, int N, int relu)
{
    __shared__ float As[2][TBM][APAD];
    __shared__ float Bs[2][TBK][BPAD];

    const int tid  = threadIdx.x;
    const int bm   = blockIdx.y * TBM;
    const int bn   = blockIdx.x * TBN;

    // global-load indexing
    const int row_a = tid >> 2;           // 0..63  (and +64)
    const int col_a = (tid & 3) << 2;     // 0,4,8,12
    const int row_b = tid >> 5;           // 0..7   (and +8)
    const int col_b = (tid & 31) << 2;    // 0..124

    // warp / lane mapping
    const int w    = tid >> 5;
    const int wm   = (w & 1) * 64;        // warp m offset
    const int wn   = (w >> 1) * 32;       // warp n offset
    const int lane = tid & 31;
    const int gid  = lane >> 2;           // group id 0..7
    const int tig  = lane & 3;            // thread in group 0..3

    float acc[4][4][4] = {};

    const int KT = K >> 4;

    float4 ra0, ra1, rb0, rb1;

    // --- load first k-tile ---
    {
        const int k0 = 0;
        ra0 = (bm + row_a      < M) ? *(const float4*)(A + (size_t)(bm + row_a)      * K + k0 + col_a) : make_float4(0,0,0,0);
        ra1 = (bm + row_a + 64 < M) ? *(const float4*)(A + (size_t)(bm + row_a + 64) * K + k0 + col_a) : make_float4(0,0,0,0);
        rb0 = *(const float4*)(W + (size_t)(k0 + row_b)     * N + bn + col_b);
        rb1 = *(const float4*)(W + (size_t)(k0 + row_b + 8) * N + bn + col_b);

        float4 t;
        t = make_float4(to_tf32(ra0.x), to_tf32(ra0.y), to_tf32(ra0.z), to_tf32(ra0.w));
        *(float4*)&As[0][row_a][col_a] = t;
        t = make_float4(to_tf32(ra1.x), to_tf32(ra1.y), to_tf32(ra1.z), to_tf32(ra1.w));
        *(float4*)&As[0][row_a + 64][col_a] = t;
        t = make_float4(to_tf32(rb0.x), to_tf32(rb0.y), to_tf32(rb0.z), to_tf32(rb0.w));
        *(float4*)&Bs[0][row_b][col_b] = t;
        t = make_float4(to_tf32(rb1.x), to_tf32(rb1.y), to_tf32(rb1.z), to_tf32(rb1.w));
        *(float4*)&Bs[0][row_b + 8][col_b] = t;
    }
    __syncthreads();

    for (int kt = 0; kt < KT; kt++) {
        const int buf = kt & 1;
        const bool has_next = (kt + 1) < KT;

        if (has_next) {
            const int k0 = (kt + 1) << 4;
            ra0 = (bm + row_a      < M) ? *(const float4*)(A + (size_t)(bm + row_a)      * K + k0 + col_a) : make_float4(0,0,0,0);
            ra1 = (bm + row_a + 64 < M) ? *(const float4*)(A + (size_t)(bm + row_a + 64) * K + k0 + col_a) : make_float4(0,0,0,0);
            rb0 = *(const float4*)(W + (size_t)(k0 + row_b)     * N + bn + col_b);
            rb1 = *(const float4*)(W + (size_t)(k0 + row_b + 8) * N + bn + col_b);
        }

        // --- compute 2 k-steps of 8 from smem[buf] ---
        #pragma unroll
        for (int ks = 0; ks < 2; ks++) {
            uint32_t af[4][4];
            uint32_t bf[4][2];
            #pragma unroll
            for (int mt = 0; mt < 4; mt++) {
                const int r0 = wm + mt * 16 + gid;
                af[mt][0] = __float_as_uint(As[buf][r0    ][ks * 8 + tig]);
                af[mt][1] = __float_as_uint(As[buf][r0 + 8][ks * 8 + tig]);
                af[mt][2] = __float_as_uint(As[buf][r0    ][ks * 8 + tig + 4]);
                af[mt][3] = __float_as_uint(As[buf][r0 + 8][ks * 8 + tig + 4]);
            }
            #pragma unroll
            for (int nt = 0; nt < 4; nt++) {
                const int c0 = wn + nt * 8 + gid;
                bf[nt][0] = __float_as_uint(Bs[buf][ks * 8 + tig    ][c0]);
                bf[nt][1] = __float_as_uint(Bs[buf][ks * 8 + tig + 4][c0]);
            }
            #pragma unroll
            for (int mt = 0; mt < 4; mt++)
                #pragma unroll
                for (int nt = 0; nt < 4; nt++)
                    mma_tf32(acc[mt][nt][0], acc[mt][nt][1], acc[mt][nt][2], acc[mt][nt][3],
                             af[mt][0], af[mt][1], af[mt][2], af[mt][3],
                             bf[nt][0], bf[nt][1]);
        }

        if (has_next) {
            const int nb = buf ^ 1;
            float4 t;
            t = make_float4(to_tf32(ra0.x), to_tf32(ra0.y), to_tf32(ra0.z), to_tf32(ra0.w));
            *(float4*)&As[nb][row_a][col_a] = t;
            t = make_float4(to_tf32(ra1.x), to_tf32(ra1.y), to_tf32(ra1.z), to_tf32(ra1.w));
            *(float4*)&As[nb][row_a + 64][col_a] = t;
            t = make_float4(to_tf32(rb0.x), to_tf32(rb0.y), to_tf32(rb0.z), to_tf32(rb0.w));
            *(float4*)&Bs[nb][row_b][col_b] = t;
            t = make_float4(to_tf32(rb1.x), to_tf32(rb1.y), to_tf32(rb1.z), to_tf32(rb1.w));
            *(float4*)&Bs[nb][row_b + 8][col_b] = t;
        }
        __syncthreads();
    }

    // --- epilogue: bias (+relu), float2 stores ---
    #pragma unroll
    for (int mt = 0; mt < 4; mt++) {
        const int r0 = bm + wm + mt * 16 + gid;
        const int r1 = r0 + 8;
        #pragma unroll
        for (int nt = 0; nt < 4; nt++) {
            const int c = bn + wn + nt * 8 + tig * 2;
            const float b0 = bias[c], b1 = bias[c + 1];
            float v0 = acc[mt][nt][0] + b0;
            float v1 = acc[mt][nt][1] + b1;
            float v2 = acc[mt][nt][2] + b0;
            float v3 = acc[mt][nt][3] + b1;
            if (relu) {
                v0 = fmaxf(v0, 0.f); v1 = fmaxf(v1, 0.f);
                v2 = fmaxf(v2, 0.f); v3 = fmaxf(v3, 0.f);
            }
            if (r0 < M) *(float2*)(C + (size_t)r0 * N + c) = make_float2(v0, v1);
            if (r1 < M) *(float2*)(C + (size_t)r1 * N + c) = make_float2(v2, v3);
        }
    }
}

// ---------------- softmax over 16 (per query-head), in place ----------------
__global__ void softmax16_kernel(float* __restrict__ a, int total) {
    int i = blockIdx.x * blockDim.x + threadIdx.x;
    if (i >= total) return;
    float* p = a + (size_t)(i >> 3) * 128 + (i & 7) * 16;
    float v[16], mx = -1e30f;
    #pragma unroll
    for (int k = 0; k < 16; k++) { v[k] = p[k]; mx = fmaxf(mx, v[k]); }
    float s = 0.f;
    #pragma unroll
    for (int k = 0; k < 16; k++) { v[k] = __expf(v[k] - mx); s += v[k]; }
    float inv = 1.f / s;
    #pragma unroll
    for (int k = 0; k < 16; k++) p[k] = v[k] * inv;
}

// ---------------- multi-scale deformable attention sampling ----------------
__global__ __launch_bounds__(256) void deform_attn_kernel(
    const float* __restrict__ v, const float* __restrict__ off,
    const float* __restrict__ aw, const float* __restrict__ ref,
    float* __restrict__ out)
{
    int gw = blockIdx.x * 8 + (threadIdx.x >> 5);
    if (gw >= MROWS * NHEAD) return;
    int lane = threadIdx.x & 31;
    int h  = gw & 7;
    int bn = gw >> 3;
    int b  = bn / NQ;
    const size_t vb = (size_t)b * NQ;

    const float* offp = off + (size_t)bn * 256 + h * 32;
    const float* awp  = aw  + (size_t)bn * 128 + h * 16;

    float acc = 0.f;

    #pragma unroll
    for (int lvl = 0; lvl < NLVL; lvl++) {
        const int W = c_w[lvl], H = c_h[lvl], S = c_start[lvl];
        const float fw = (float)W, fh = (float)H;
        float rx = ref[((size_t)bn * NLVL + lvl) * 2 + 0];
        float ry = ref[((size_t)bn * NLVL + lvl) * 2 + 1];

        #pragma unroll
        for (int p = 0; p < NPNT; p++) {
            float ox = offp[(lvl * NPNT + p) * 2 + 0];
            float oy = offp[(lvl * NPNT + p) * 2 + 1];
            float a  = awp[lvl * NPNT + p];

            float locx = rx + ox / fw;
            float locy = ry + oy / fh;
            float xs = locx * fw - 0.5f;
            float ys = locy * fh - 0.5f;

            float fxs = floorf(xs), fys = floorf(ys);
            int x0 = (int)fxs, y0 = (int)fys;
            float lx = xs - fxs, ly = ys - fys;

            float w00 = (1.f - lx) * (1.f - ly) * a;
            float w01 = lx * (1.f - ly) * a;
            float w10 = (1.f - lx) * ly * a;
            float w11 = lx * ly * a;

            int x1 = x0 + 1, y1 = y0 + 1;
            bool vx0 = (x0 >= 0) & (x0 < W);
            bool vx1 = (x1 >= 0) & (x1 < W);
            bool vy0 = (y0 >= 0) & (y0 < H);
            bool vy1 = (y1 >= 0) & (y1 < H);

            if (vy0 & vx0) acc += w00 * v[(vb + S + (size_t)y0 * W + x0) * E_ + h * HDIM + lane];
            if (vy0 & vx1) acc += w01 * v[(vb + S + (size_t)y0 * W + x1) * E_ + h * HDIM + lane];
            if (vy1 & vx0) acc += w10 * v[(vb + S + (size_t)y1 * W + x0) * E_ + h * HDIM + lane];
            if (vy1 & vx1) acc += w11 * v[(vb + S + (size_t)y1 * W + x1) * E_ + h * HDIM + lane];
        }
    }
    out[(size_t)bn * E_ + h * HDIM + lane] = acc;
}

// ---------------- fused residual add + LayerNorm (warp per row) ----------------
__global__ __launch_bounds__(256) void add_ln_kernel(
    const float* __restrict__ x, const float* __restrict__ r,
    const float* __restrict__ gamma, const float* __restrict__ beta,
    float* __restrict__ out, int M)
{
    int row = blockIdx.x * 8 + (threadIdx.x >> 5);
    if (row >= M) return;
    int lane = threadIdx.x & 31;

    const float* xp = x + (size_t)row * E_;
    const float* rp = r + (size_t)row * E_;

    float vals[8];
    float s = 0.f;
    #pragma unroll
    for (int i = 0; i < 8; i++) {
        vals[i] = xp[lane + i * 32] + rp[lane + i * 32];
        s += vals[i];
    }
    #pragma unroll
    for (int o = 16; o > 0; o >>= 1) s += __shfl_xor_sync(0xFFFFFFFFu, s, o);
    float mean = s * (1.f / E_);

    float vs = 0.f;
    #pragma unroll
    for (int i = 0; i < 8; i++) {
        float d = vals[i] - mean;
        vs += d * d;
    }
    #pragma unroll
    for (int o = 16; o > 0; o >>= 1) vs += __shfl_xor_sync(0xFFFFFFFFu, vs, o);
    float inv = rsqrtf(vs * (1.f / E_) + EPS);

    float* op = out + (size_t)row * E_;
    #pragma unroll
    for (int i = 0; i < 8; i++) {
        int c = lane + i * 32;
        op[c] = (vals[i] - mean) * inv * gamma[c] + beta[c];
    }
}

// ---------------- launcher ----------------
static inline void run_gemm(const float* A, const float* W, const float* b,
                            float* C, int M, int K, int Nc, int relu) {
    dim3 grid(Nc / TBN, (M + TBM - 1) / TBM);
    gemm_tf32<<<grid, 256>>>(A, W, b, C, M, K, Nc, relu);
}

extern "C" void kernel_launch(void* const* d_in, const int* in_sizes, int n_in,
                              void* d_out, int out_size) {
    const float* src  = (const float*)d_in[0];
    const float* ref  = (const float*)d_in[1];
    const float* Woff = (const float*)d_in[4];
    const float* boff = (const float*)d_in[5];
    const float* Waw  = (const float*)d_in[6];
    const float* baw  = (const float*)d_in[7];
    const float* Wv   = (const float*)d_in[8];
    const float* bv   = (const float*)d_in[9];
    const float* Wo   = (const float*)d_in[10];
    const float* bo   = (const float*)d_in[11];
    const float* ln1g = (const float*)d_in[12];
    const float* ln1b = (const float*)d_in[13];
    const float* Wf1  = (const float*)d_in[14];
    const float* bf1  = (const float*)d_in[15];
    const float* Wf2  = (const float*)d_in[16];
    const float* bf2  = (const float*)d_in[17];
    const float* ln2g = (const float*)d_in[18];
    const float* ln2b = (const float*)d_in[19];
    float* out = (float*)d_out;

    float *px, *pv, *poff, *pawl, *psamp, *ptmp, *pffn;
    cudaGetSymbolAddress((void**)&px,    g_x);
    cudaGetSymbolAddress((void**)&pv,    g_v);
    cudaGetSymbolAddress((void**)&poff,  g_off);
    cudaGetSymbolAddress((void**)&pawl,  g_awl);
    cudaGetSymbolAddress((void**)&psamp, g_samp);
    cudaGetSymbolAddress((void**)&ptmp,  g_tmp);
    cudaGetSymbolAddress((void**)&pffn,  g_ffn);

    const int M = MROWS;
    const int nElem = M * E_;

    copy_kernel<<<(nElem + 255) / 256, 256>>>(src, px, nElem);

    for (int layer = 0; layer < 6; layer++) {
        run_gemm(px, Wv,   bv,   pv,   M, E_, E_,  0);
        run_gemm(px, Woff, boff, poff, M, E_, 256, 0);
        run_gemm(px, Waw,  baw,  pawl, M, E_, 128, 0);

        softmax16_kernel<<<(M * NHEAD + 255) / 256, 256>>>(pawl, M * NHEAD);

        deform_attn_kernel<<<M, 256>>>(pv, poff, pawl, ref, psamp);

        run_gemm(psamp, Wo, bo, ptmp, M, E_, E_, 0);
        add_ln_kernel<<<(M + 7) / 8, 256>>>(px, ptmp, ln1g, ln1b, px, M);

        run_gemm(px,   Wf1, bf1, pffn, M, E_, F_, 1);
        run_gemm(pffn, Wf2, bf2, ptmp, M, F_, E_, 0);

        float* dst = (layer == 5) ? out : px;
        add_ln_kernel<<<(M + 7) / 8, 256>>>(px, ptmp, ln2g, ln2b, dst, M);
    }
}

// round 3
// speedup vs baseline: 2.0702x; 1.0699x over previous
#include <cuda_runtime.h>
#include <math.h>
#include <stdint.h>

// ---------------- static problem config ----------------
#define NQ     13294
#define BATCH  2
#define MROWS  (BATCH * NQ)     // 26588
#define E_     256
#define F_     1024
#define CATN   640              // concat proj width: 256 (v) + 256 (off) + 128 (aw)
#define NHEAD  8
#define HDIM   32
#define NLVL   4
#define NPNT   4
#define EPS    1e-5f

// ---------------- scratch (static device globals; no allocation) ----------------
__device__ float g_x   [MROWS * E_];
__device__ float g_voa [MROWS * CATN];   // [v | off | aw] per row
__device__ float g_samp[MROWS * E_];
__device__ float g_tmp [MROWS * E_];
__device__ float g_ffn [MROWS * F_];
__device__ float g_wcat[E_ * CATN];
__device__ float g_bcat[CATN];

__constant__ int c_w[NLVL]     = {100, 50, 25, 13};
__constant__ int c_h[NLVL]     = {100, 50, 25, 13};
__constant__ int c_start[NLVL] = {0, 10000, 12500, 13125};

// ---------------- utility ----------------
__global__ void copy_kernel(const float* __restrict__ src, float* __restrict__ dst, int n) {
    int i = blockIdx.x * blockDim.x + threadIdx.x;
    if (i < n) dst[i] = src[i];
}

__global__ void concat_w_kernel(
    const float* __restrict__ Wv, const float* __restrict__ Woff, const float* __restrict__ Waw,
    const float* __restrict__ bv, const float* __restrict__ boff, const float* __restrict__ baw,
    float* __restrict__ Wcat, float* __restrict__ bcat)
{
    int i = blockIdx.x * blockDim.x + threadIdx.x;
    if (i < E_ * CATN) {
        int r = i / CATN, c = i % CATN;
        float v;
        if (c < 256)      v = Wv  [r * 256 + c];
        else if (c < 512) v = Woff[r * 256 + (c - 256)];
        else              v = Waw [r * 128 + (c - 512)];
        Wcat[i] = v;
    }
    if (i < CATN) {
        bcat[i] = (i < 256) ? bv[i] : (i < 512) ? boff[i - 256] : baw[i - 512];
    }
}

// ---------------- cp.async helpers ----------------
__device__ __forceinline__ void cp_async16(void* smem_dst, const void* gmem_src, bool pred) {
    uint32_t saddr = (uint32_t)__cvta_generic_to_shared(smem_dst);
    int sz = pred ? 16 : 0;
    asm volatile("cp.async.cg.shared.global [%0], [%1], 16, %2;\n"
                 :: "r"(saddr), "l"(gmem_src), "r"(sz));
}
#define CP_COMMIT() asm volatile("cp.async.commit_group;\n" ::: "memory")
#define CP_WAIT0()  asm volatile("cp.async.wait_group 0;\n" ::: "memory")

// ---------------- TF32 tensor-core GEMM ----------------
// C = act(A[MxK] * W[KxN] + bias), 128x128x16 CTA tile, 256 threads (8 warps 2x4),
// warp tile 64x32 via 4x4 mma.m16n8k8, cp.async double-buffered smem.
// f32 fed raw to tf32 mma (hardware truncation).
#define TBM 128
#define TBN 128
#define TBK 16
#define APAD 20   // As row stride (floats): conflict-free, 16B-aligned rows (80B = 5*16)
#define BPAD 136  // Bs row stride

__device__ __forceinline__ void mma_tf32(
    float& d0, float& d1, float& d2, float& d3,
    uint32_t a0, uint32_t a1, uint32_t a2, uint32_t a3,
    uint32_t b0, uint32_t b1)
{
    asm volatile(
        "mma.sync.aligned.m16n8k8.row.col.f32.tf32.tf32.f32 "
        "{%0,%1,%2,%3}, {%4,%5,%6,%7}, {%8,%9}, {%0,%1,%2,%3};"
        : "+f"(d0), "+f"(d1), "+f"(d2), "+f"(d3)
        : "r"(a0), "r"(a1), "r"(a2), "r"(a3), "r"(b0), "r"(b1));
}

__global__ __launch_bounds__(256, 2) void gemm_tf32(
    const float* __restrict__ A, const float* __restrict__ W,
    const float* __restrict__ bias, float* __restrict__ C,
    int M, int K, int N, int relu)
{
    __shared__ float As[2][TBM][APAD];
    __shared__ float Bs[2][TBK][BPAD];

    const int tid = threadIdx.x;
    const int bm  = blockIdx.y * TBM;
    const int bn  = blockIdx.x * TBN;

    // global-load indexing (16B per thread)
    const int row_a = tid >> 2;           // 0..63  (and +64)
    const int col_a = (tid & 3) << 2;     // 0,4,8,12
    const int row_b = tid >> 5;           // 0..7   (and +8)
    const int col_b = (tid & 31) << 2;    // 0..124

    const bool a0_ok = (bm + row_a)      < M;
    const bool a1_ok = (bm + row_a + 64) < M;

    // warp / lane mapping
    const int w    = tid >> 5;
    const int wm   = (w & 1) * 64;
    const int wn   = (w >> 1) * 32;
    const int lane = tid & 31;
    const int gid  = lane >> 2;
    const int tig  = lane & 3;

    float acc[4][4][4] = {};

    const int KT = K >> 4;

    const float* Abase0 = A + (size_t)(bm + row_a)      * K + col_a;
    const float* Abase1 = A + (size_t)(bm + row_a + 64) * K + col_a;
    const float* Bbase0 = W + (size_t)row_b       * N + bn + col_b;
    const float* Bbase1 = W + (size_t)(row_b + 8) * N + bn + col_b;

    // prologue: stage 0
    {
        cp_async16(&As[0][row_a][col_a],      Abase0, a0_ok);
        cp_async16(&As[0][row_a + 64][col_a], Abase1, a1_ok);
        cp_async16(&Bs[0][row_b][col_b],      Bbase0, true);
        cp_async16(&Bs[0][row_b + 8][col_b],  Bbase1, true);
        CP_COMMIT();
    }

    for (int kt = 0; kt < KT; kt++) {
        const int buf = kt & 1;
        CP_WAIT0();
        __syncthreads();

        // issue next tile load (overlaps with compute below)
        if (kt + 1 < KT) {
            const int k0 = (kt + 1) << 4;
            const int nb = buf ^ 1;
            cp_async16(&As[nb][row_a][col_a],      Abase0 + k0, a0_ok);
            cp_async16(&As[nb][row_a + 64][col_a], Abase1 + k0, a1_ok);
            cp_async16(&Bs[nb][row_b][col_b],      Bbase0 + (size_t)k0 * N, true);
            cp_async16(&Bs[nb][row_b + 8][col_b],  Bbase1 + (size_t)k0 * N, true);
            CP_COMMIT();
        }

        #pragma unroll
        for (int ks = 0; ks < 2; ks++) {
            uint32_t af[4][4];
            uint32_t bf[4][2];
            #pragma unroll
            for (int mt = 0; mt < 4; mt++) {
                const int r0 = wm + mt * 16 + gid;
                af[mt][0] = __float_as_uint(As[buf][r0    ][ks * 8 + tig]);
                af[mt][1] = __float_as_uint(As[buf][r0 + 8][ks * 8 + tig]);
                af[mt][2] = __float_as_uint(As[buf][r0    ][ks * 8 + tig + 4]);
                af[mt][3] = __float_as_uint(As[buf][r0 + 8][ks * 8 + tig + 4]);
            }
            #pragma unroll
            for (int nt = 0; nt < 4; nt++) {
                const int c0 = wn + nt * 8 + gid;
                bf[nt][0] = __float_as_uint(Bs[buf][ks * 8 + tig    ][c0]);
                bf[nt][1] = __float_as_uint(Bs[buf][ks * 8 + tig + 4][c0]);
            }
            #pragma unroll
            for (int mt = 0; mt < 4; mt++)
                #pragma unroll
                for (int nt = 0; nt < 4; nt++)
                    mma_tf32(acc[mt][nt][0], acc[mt][nt][1], acc[mt][nt][2], acc[mt][nt][3],
                             af[mt][0], af[mt][1], af[mt][2], af[mt][3],
                             bf[nt][0], bf[nt][1]);
        }
        __syncthreads();
    }

    // epilogue: bias (+relu), float2 stores
    #pragma unroll
    for (int mt = 0; mt < 4; mt++) {
        const int r0 = bm + wm + mt * 16 + gid;
        const int r1 = r0 + 8;
        #pragma unroll
        for (int nt = 0; nt < 4; nt++) {
            const int c = bn + wn + nt * 8 + tig * 2;
            const float b0 = bias[c], b1 = bias[c + 1];
            float v0 = acc[mt][nt][0] + b0;
            float v1 = acc[mt][nt][1] + b1;
            float v2 = acc[mt][nt][2] + b0;
            float v3 = acc[mt][nt][3] + b1;
            if (relu) {
                v0 = fmaxf(v0, 0.f); v1 = fmaxf(v1, 0.f);
                v2 = fmaxf(v2, 0.f); v3 = fmaxf(v3, 0.f);
            }
            if (r0 < M) *(float2*)(C + (size_t)r0 * N + c) = make_float2(v0, v1);
            if (r1 < M) *(float2*)(C + (size_t)r1 * N + c) = make_float2(v2, v3);
        }
    }
}

// ---------------- softmax over 16 (per query-head), in place on g_voa cols 512..639 ----------------
__global__ void softmax16_kernel(float* __restrict__ voa, int total) {
    int i = blockIdx.x * blockDim.x + threadIdx.x;   // i = bn*8 + h
    if (i >= total) return;
    float* p = voa + (size_t)(i >> 3) * CATN + 512 + (i & 7) * 16;
    float v[16], mx = -1e30f;
    #pragma unroll
    for (int k = 0; k < 16; k++) { v[k] = p[k]; mx = fmaxf(mx, v[k]); }
    float s = 0.f;
    #pragma unroll
    for (int k = 0; k < 16; k++) { v[k] = __expf(v[k] - mx); s += v[k]; }
    float inv = 1.f / s;
    #pragma unroll
    for (int k = 0; k < 16; k++) p[k] = v[k] * inv;
}

// ---------------- multi-scale deformable attention sampling ----------------
// one warp per (bn, head); lane = channel. v/off/aw all live in g_voa (row stride CATN).
__global__ __launch_bounds__(256) void deform_attn_kernel(
    const float* __restrict__ voa, const float* __restrict__ ref,
    float* __restrict__ out)
{
    int gw = blockIdx.x * 8 + (threadIdx.x >> 5);
    if (gw >= MROWS * NHEAD) return;
    int lane = threadIdx.x & 31;
    int h  = gw & 7;
    int bn = gw >> 3;
    int b  = bn / NQ;
    const size_t vb = (size_t)b * NQ;

    const float* offp = voa + (size_t)bn * CATN + 256 + h * 32;  // (L,P,2)
    const float* awp  = voa + (size_t)bn * CATN + 512 + h * 16;  // (L,P)

    float acc = 0.f;

    #pragma unroll
    for (int lvl = 0; lvl < NLVL; lvl++) {
        const int W = c_w[lvl], H = c_h[lvl], S = c_start[lvl];
        const float fw = (float)W, fh = (float)H;
        float rx = ref[((size_t)bn * NLVL + lvl) * 2 + 0];
        float ry = ref[((size_t)bn * NLVL + lvl) * 2 + 1];

        #pragma unroll
        for (int p = 0; p < NPNT; p++) {
            float ox = offp[(lvl * NPNT + p) * 2 + 0];
            float oy = offp[(lvl * NPNT + p) * 2 + 1];
            float a  = awp[lvl * NPNT + p];

            float locx = rx + ox / fw;
            float locy = ry + oy / fh;
            float xs = locx * fw - 0.5f;
            float ys = locy * fh - 0.5f;

            float fxs = floorf(xs), fys = floorf(ys);
            int x0 = (int)fxs, y0 = (int)fys;
            float lx = xs - fxs, ly = ys - fys;

            float w00 = (1.f - lx) * (1.f - ly) * a;
            float w01 = lx * (1.f - ly) * a;
            float w10 = (1.f - lx) * ly * a;
            float w11 = lx * ly * a;

            int x1 = x0 + 1, y1 = y0 + 1;
            bool vx0 = (x0 >= 0) & (x0 < W);
            bool vx1 = (x1 >= 0) & (x1 < W);
            bool vy0 = (y0 >= 0) & (y0 < H);
            bool vy1 = (y1 >= 0) & (y1 < H);

            if (vy0 & vx0) acc += w00 * voa[(vb + S + (size_t)y0 * W + x0) * CATN + h * HDIM + lane];
            if (vy0 & vx1) acc += w01 * voa[(vb + S + (size_t)y0 * W + x1) * CATN + h * HDIM + lane];
            if (vy1 & vx0) acc += w10 * voa[(vb + S + (size_t)y1 * W + x0) * CATN + h * HDIM + lane];
            if (vy1 & vx1) acc += w11 * voa[(vb + S + (size_t)y1 * W + x1) * CATN + h * HDIM + lane];
        }
    }
    out[(size_t)bn * E_ + h * HDIM + lane] = acc;
}

// ---------------- fused residual add + LayerNorm (warp per row) ----------------
__global__ __launch_bounds__(256) void add_ln_kernel(
    const float* __restrict__ x, const float* __restrict__ r,
    const float* __restrict__ gamma, const float* __restrict__ beta,
    float* __restrict__ out, int M)
{
    int row = blockIdx.x * 8 + (threadIdx.x >> 5);
    if (row >= M) return;
    int lane = threadIdx.x & 31;

    const float* xp = x + (size_t)row * E_;
    const float* rp = r + (size_t)row * E_;

    float vals[8];
    float s = 0.f;
    #pragma unroll
    for (int i = 0; i < 8; i++) {
        vals[i] = xp[lane + i * 32] + rp[lane + i * 32];
        s += vals[i];
    }
    #pragma unroll
    for (int o = 16; o > 0; o >>= 1) s += __shfl_xor_sync(0xFFFFFFFFu, s, o);
    float mean = s * (1.f / E_);

    float vs = 0.f;
    #pragma unroll
    for (int i = 0; i < 8; i++) {
        float d = vals[i] - mean;
        vs += d * d;
    }
    #pragma unroll
    for (int o = 16; o > 0; o >>= 1) vs += __shfl_xor_sync(0xFFFFFFFFu, vs, o);
    float inv = rsqrtf(vs * (1.f / E_) + EPS);

    float* op = out + (size_t)row * E_;
    #pragma unroll
    for (int i = 0; i < 8; i++) {
        int c = lane + i * 32;
        op[c] = (vals[i] - mean) * inv * gamma[c] + beta[c];
    }
}

// ---------------- launcher ----------------
static inline void run_gemm(const float* A, const float* W, const float* b,
                            float* C, int M, int K, int Nc, int relu) {
    dim3 grid(Nc / TBN, (M + TBM - 1) / TBM);
    gemm_tf32<<<grid, 256>>>(A, W, b, C, M, K, Nc, relu);
}

extern "C" void kernel_launch(void* const* d_in, const int* in_sizes, int n_in,
                              void* d_out, int out_size) {
    const float* src  = (const float*)d_in[0];
    const float* ref  = (const float*)d_in[1];
    const float* Woff = (const float*)d_in[4];
    const float* boff = (const float*)d_in[5];
    const float* Waw  = (const float*)d_in[6];
    const float* baw  = (const float*)d_in[7];
    const float* Wv   = (const float*)d_in[8];
    const float* bv   = (const float*)d_in[9];
    const float* Wo   = (const float*)d_in[10];
    const float* bo   = (const float*)d_in[11];
    const float* ln1g = (const float*)d_in[12];
    const float* ln1b = (const float*)d_in[13];
    const float* Wf1  = (const float*)d_in[14];
    const float* bf1  = (const float*)d_in[15];
    const float* Wf2  = (const float*)d_in[16];
    const float* bf2  = (const float*)d_in[17];
    const float* ln2g = (const float*)d_in[18];
    const float* ln2b = (const float*)d_in[19];
    float* out = (float*)d_out;

    float *px, *pvoa, *psamp, *ptmp, *pffn, *pwcat, *pbcat;
    cudaGetSymbolAddress((void**)&px,    g_x);
    cudaGetSymbolAddress((void**)&pvoa,  g_voa);
    cudaGetSymbolAddress((void**)&psamp, g_samp);
    cudaGetSymbolAddress((void**)&ptmp,  g_tmp);
    cudaGetSymbolAddress((void**)&pffn,  g_ffn);
    cudaGetSymbolAddress((void**)&pwcat, g_wcat);
    cudaGetSymbolAddress((void**)&pbcat, g_bcat);

    const int M = MROWS;
    const int nElem = M * E_;

    copy_kernel<<<(nElem + 255) / 256, 256>>>(src, px, nElem);
    concat_w_kernel<<<(E_ * CATN + 255) / 256, 256>>>(Wv, Woff, Waw, bv, boff, baw, pwcat, pbcat);

    for (int layer = 0; layer < 6; layer++) {
        // fused projections: [v | off | aw]
        run_gemm(px, pwcat, pbcat, pvoa, M, E_, CATN, 0);

        softmax16_kernel<<<(M * NHEAD + 255) / 256, 256>>>(pvoa, M * NHEAD);

        deform_attn_kernel<<<M, 256>>>(pvoa, ref, psamp);

        run_gemm(psamp, Wo, bo, ptmp, M, E_, E_, 0);
        add_ln_kernel<<<(M + 7) / 8, 256>>>(px, ptmp, ln1g, ln1b, px, M);

        run_gemm(px,   Wf1, bf1, pffn, M, E_, F_, 1);
        run_gemm(pffn, Wf2, bf2, ptmp, M, F_, E_, 0);

        float* dst = (layer == 5) ? out : px;
        add_ln_kernel<<<(M + 7) / 8, 256>>>(px, ptmp, ln2g, ln2b, dst, M);
    }
}

// round 4
// speedup vs baseline: 2.4880x; 1.2018x over previous
#include <cuda_runtime.h>
#include <math.h>
#include <stdint.h>

// ---------------- static problem config ----------------
#define NQ     13294
#define BATCH  2
#define MROWS  (BATCH * NQ)     // 26588
#define E_     256
#define F_     1024
#define CATN   640              // concat proj width: 256 (v) + 256 (off) + 128 (aw)
#define NHEAD  8
#define HDIM   32
#define NLVL   4
#define NPNT   4
#define EPS    1e-5f

// ---------------- scratch (static device globals; no allocation) ----------------
__device__ float g_x   [MROWS * E_];
__device__ float g_voa [MROWS * CATN];   // [v | off | aw(probs)] per row
__device__ float g_samp[MROWS * E_];
__device__ float g_tmp [MROWS * E_];
__device__ float g_ffn [MROWS * F_];
__device__ float g_wcat[E_ * CATN];      // tf32-rounded concat weights
__device__ float g_bcat[CATN];
__device__ float g_wo  [E_ * E_];        // tf32-rounded Wo
__device__ float g_wf1 [E_ * F_];        // tf32-rounded Wf1
__device__ float g_wf2 [F_ * E_];        // tf32-rounded Wf2

__constant__ int c_w[NLVL]     = {100, 50, 25, 13};
__constant__ int c_h[NLVL]     = {100, 50, 25, 13};
__constant__ int c_start[NLVL] = {0, 10000, 12500, 13125};

__device__ __forceinline__ float to_tf32(float x) {
    float r;
    asm("cvt.rna.tf32.f32 %0, %1;" : "=f"(r) : "f"(x));
    return r;
}

// ---------------- utility ----------------
__global__ void round_copy_kernel(const float* __restrict__ src, float* __restrict__ dst, int n) {
    int i = blockIdx.x * blockDim.x + threadIdx.x;
    if (i < n) dst[i] = to_tf32(src[i]);
}

__global__ void concat_w_kernel(
    const float* __restrict__ Wv, const float* __restrict__ Woff, const float* __restrict__ Waw,
    const float* __restrict__ bv, const float* __restrict__ boff, const float* __restrict__ baw,
    float* __restrict__ Wcat, float* __restrict__ bcat)
{
    int i = blockIdx.x * blockDim.x + threadIdx.x;
    if (i < E_ * CATN) {
        int r = i / CATN, c = i % CATN;
        float v;
        if (c < 256)      v = Wv  [r * 256 + c];
        else if (c < 512) v = Woff[r * 256 + (c - 256)];
        else              v = Waw [r * 128 + (c - 512)];
        Wcat[i] = to_tf32(v);
    }
    if (i < CATN) {
        bcat[i] = (i < 256) ? bv[i] : (i < 512) ? boff[i - 256] : baw[i - 512];
    }
}

// ---------------- cp.async helpers ----------------
__device__ __forceinline__ void cp_async16(void* smem_dst, const void* gmem_src, bool pred) {
    uint32_t saddr = (uint32_t)__cvta_generic_to_shared(smem_dst);
    int sz = pred ? 16 : 0;
    asm volatile("cp.async.cg.shared.global [%0], [%1], 16, %2;\n"
                 :: "r"(saddr), "l"(gmem_src), "r"(sz));
}
#define CP_COMMIT() asm volatile("cp.async.commit_group;\n" ::: "memory")
#define CP_WAIT1()  asm volatile("cp.async.wait_group 1;\n" ::: "memory")

// ---------------- TF32 tensor-core GEMM ----------------
// C = act(A[MxK] * W[KxN] + bias), 128x128x16 CTA tile, 256 threads (8 warps 2x4),
// warp tile 64x32 via 4x4 mma.m16n8k8, 3-stage cp.async pipeline, dynamic smem.
// Inputs are pre-rounded to tf32 by producers; mma consumes raw bits.
#define TBM 128
#define TBN 128
#define TBK 16
#define APAD 20    // As row stride (floats)
#define BPAD 136   // Bs row stride
#define NSTAGE 3
#define AS_STAGE (TBM * APAD)        // 2560 floats
#define BS_STAGE (TBK * BPAD)        // 2176 floats
#define GEMM_SMEM_BYTES ((NSTAGE * (AS_STAGE + BS_STAGE)) * 4)   // 56832

__device__ __forceinline__ void mma_tf32(
    float& d0, float& d1, float& d2, float& d3,
    uint32_t a0, uint32_t a1, uint32_t a2, uint32_t a3,
    uint32_t b0, uint32_t b1)
{
    asm volatile(
        "mma.sync.aligned.m16n8k8.row.col.f32.tf32.tf32.f32 "
        "{%0,%1,%2,%3}, {%4,%5,%6,%7}, {%8,%9}, {%0,%1,%2,%3};"
        : "+f"(d0), "+f"(d1), "+f"(d2), "+f"(d3)
        : "r"(a0), "r"(a1), "r"(a2), "r"(a3), "r"(b0), "r"(b1));
}

__global__ __launch_bounds__(256, 2) void gemm_tf32(
    const float* __restrict__ A, const float* __restrict__ W,
    const float* __restrict__ bias, float* __restrict__ C,
    int M, int K, int N, int relu, int round_out)
{
    extern __shared__ float sm[];
    float* Asm = sm;                          // NSTAGE * AS_STAGE
    float* Bsm = sm + NSTAGE * AS_STAGE;      // NSTAGE * BS_STAGE

    const int tid = threadIdx.x;
    const int bm  = blockIdx.y * TBM;
    const int bn  = blockIdx.x * TBN;

    const int row_a = tid >> 2;           // 0..63  (and +64)
    const int col_a = (tid & 3) << 2;     // 0,4,8,12
    const int row_b = tid >> 5;           // 0..7   (and +8)
    const int col_b = (tid & 31) << 2;    // 0..124

    const bool a0_ok = (bm + row_a)      < M;
    const bool a1_ok = (bm + row_a + 64) < M;

    const int w    = tid >> 5;
    const int wm   = (w & 1) * 64;
    const int wn   = (w >> 1) * 32;
    const int lane = tid & 31;
    const int gid  = lane >> 2;
    const int tig  = lane & 3;

    float acc[4][4][4] = {};

    const int KT = K >> 4;

    const float* Abase0 = A + (size_t)(bm + row_a)      * K + col_a;
    const float* Abase1 = A + (size_t)(bm + row_a + 64) * K + col_a;
    const float* Bbase0 = W + (size_t)row_b       * N + bn + col_b;
    const float* Bbase1 = W + (size_t)(row_b + 8) * N + bn + col_b;

    // per-thread staging targets
    float* asm_dst0[NSTAGE];
    float* asm_dst1[NSTAGE];
    float* bsm_dst0[NSTAGE];
    float* bsm_dst1[NSTAGE];
    #pragma unroll
    for (int s = 0; s < NSTAGE; s++) {
        asm_dst0[s] = Asm + s * AS_STAGE + row_a * APAD + col_a;
        asm_dst1[s] = Asm + s * AS_STAGE + (row_a + 64) * APAD + col_a;
        bsm_dst0[s] = Bsm + s * BS_STAGE + row_b * BPAD + col_b;
        bsm_dst1[s] = Bsm + s * BS_STAGE + (row_b + 8) * BPAD + col_b;
    }

    // prologue: issue stages 0..NSTAGE-2
    #pragma unroll
    for (int s = 0; s < NSTAGE - 1; s++) {
        const int k0 = s << 4;
        cp_async16(asm_dst0[s], Abase0 + k0, a0_ok);
        cp_async16(asm_dst1[s], Abase1 + k0, a1_ok);
        cp_async16(bsm_dst0[s], Bbase0 + (size_t)k0 * N, true);
        cp_async16(bsm_dst1[s], Bbase1 + (size_t)k0 * N, true);
        CP_COMMIT();
    }

    for (int kt = 0; kt < KT; kt++) {
        CP_WAIT1();            // tile kt resident
        __syncthreads();       // visibility + buffer-reuse fence

        // issue tile kt+2 into buffer (kt+2)%3 (was read at iter kt-1)
        if (kt + NSTAGE - 1 < KT) {
            const int s  = (kt + NSTAGE - 1) % NSTAGE;
            const int k0 = (kt + NSTAGE - 1) << 4;
            cp_async16(asm_dst0[s], Abase0 + k0, a0_ok);
            cp_async16(asm_dst1[s], Abase1 + k0, a1_ok);
            cp_async16(bsm_dst0[s], Bbase0 + (size_t)k0 * N, true);
            cp_async16(bsm_dst1[s], Bbase1 + (size_t)k0 * N, true);
        }
        CP_COMMIT();

        const float* Ab = Asm + (kt % NSTAGE) * AS_STAGE;
        const float* Bb = Bsm + (kt % NSTAGE) * BS_STAGE;

        #pragma unroll
        for (int ks = 0; ks < 2; ks++) {
            uint32_t af[4][4];
            uint32_t bf[4][2];
            #pragma unroll
            for (int mt = 0; mt < 4; mt++) {
                const int r0 = wm + mt * 16 + gid;
                af[mt][0] = __float_as_uint(Ab[(r0    ) * APAD + ks * 8 + tig]);
                af[mt][1] = __float_as_uint(Ab[(r0 + 8) * APAD + ks * 8 + tig]);
                af[mt][2] = __float_as_uint(Ab[(r0    ) * APAD + ks * 8 + tig + 4]);
                af[mt][3] = __float_as_uint(Ab[(r0 + 8) * APAD + ks * 8 + tig + 4]);
            }
            #pragma unroll
            for (int nt = 0; nt < 4; nt++) {
                const int c0 = wn + nt * 8 + gid;
                bf[nt][0] = __float_as_uint(Bb[(ks * 8 + tig    ) * BPAD + c0]);
                bf[nt][1] = __float_as_uint(Bb[(ks * 8 + tig + 4) * BPAD + c0]);
            }
            #pragma unroll
            for (int mt = 0; mt < 4; mt++)
                #pragma unroll
                for (int nt = 0; nt < 4; nt++)
                    mma_tf32(acc[mt][nt][0], acc[mt][nt][1], acc[mt][nt][2], acc[mt][nt][3],
                             af[mt][0], af[mt][1], af[mt][2], af[mt][3],
                             bf[nt][0], bf[nt][1]);
        }
    }

    // epilogue: bias (+relu) (+tf32 round), float2 stores
    #pragma unroll
    for (int mt = 0; mt < 4; mt++) {
        const int r0 = bm + wm + mt * 16 + gid;
        const int r1 = r0 + 8;
        #pragma unroll
        for (int nt = 0; nt < 4; nt++) {
            const int c = bn + wn + nt * 8 + tig * 2;
            const float b0 = bias[c], b1 = bias[c + 1];
            float v0 = acc[mt][nt][0] + b0;
            float v1 = acc[mt][nt][1] + b1;
            float v2 = acc[mt][nt][2] + b0;
            float v3 = acc[mt][nt][3] + b1;
            if (relu) {
                v0 = fmaxf(v0, 0.f); v1 = fmaxf(v1, 0.f);
                v2 = fmaxf(v2, 0.f); v3 = fmaxf(v3, 0.f);
            }
            if (round_out) {
                v0 = to_tf32(v0); v1 = to_tf32(v1);
                v2 = to_tf32(v2); v3 = to_tf32(v3);
            }
            if (r0 < M) *(float2*)(C + (size_t)r0 * N + c) = make_float2(v0, v1);
            if (r1 < M) *(float2*)(C + (size_t)r1 * N + c) = make_float2(v2, v3);
        }
    }
}

// ---------------- multi-scale deformable attention (softmax fused) ----------------
// one warp per (bn, head); lane = channel. logits/off/v live in g_voa (row stride CATN).
__global__ __launch_bounds__(256) void deform_attn_kernel(
    const float* __restrict__ voa, const float* __restrict__ ref,
    float* __restrict__ out)
{
    int gw = blockIdx.x * 8 + (threadIdx.x >> 5);
    if (gw >= MROWS * NHEAD) return;
    int lane = threadIdx.x & 31;
    int h  = gw & 7;
    int bn = gw >> 3;
    int b  = bn / NQ;
    const size_t vb = (size_t)b * NQ;

    const float* offp = voa + (size_t)bn * CATN + 256 + h * 32;  // (L,P,2)
    const float* awp  = voa + (size_t)bn * CATN + 512 + h * 16;  // (L,P) logits

    // inline softmax over 16 logits (each 16-lane half holds identical copy)
    float logit = awp[lane & 15];
    float mx = logit;
    #pragma unroll
    for (int o = 8; o > 0; o >>= 1) mx = fmaxf(mx, __shfl_xor_sync(0xFFFFFFFFu, mx, o));
    float e = __expf(logit - mx);
    float ssum = e;
    #pragma unroll
    for (int o = 8; o > 0; o >>= 1) ssum += __shfl_xor_sync(0xFFFFFFFFu, ssum, o);
    float prob = e / ssum;

    const float* vch = voa + (vb) * CATN + h * HDIM + lane;

    float acc = 0.f;

    #pragma unroll
    for (int lvl = 0; lvl < NLVL; lvl++) {
        const int W = c_w[lvl], H = c_h[lvl], S = c_start[lvl];
        const float fw = (float)W, fh = (float)H;
        float rx = ref[((size_t)bn * NLVL + lvl) * 2 + 0];
        float ry = ref[((size_t)bn * NLVL + lvl) * 2 + 1];

        #pragma unroll
        for (int p = 0; p < NPNT; p++) {
            float ox = offp[(lvl * NPNT + p) * 2 + 0];
            float oy = offp[(lvl * NPNT + p) * 2 + 1];
            float a  = __shfl_sync(0xFFFFFFFFu, prob, lvl * NPNT + p, 16);

            float locx = rx + ox / fw;
            float locy = ry + oy / fh;
            float xs = locx * fw - 0.5f;
            float ys = locy * fh - 0.5f;

            float fxs = floorf(xs), fys = floorf(ys);
            int x0 = (int)fxs, y0 = (int)fys;
            float lx = xs - fxs, ly = ys - fys;

            float w00 = (1.f - lx) * (1.f - ly) * a;
            float w01 = lx * (1.f - ly) * a;
            float w10 = (1.f - lx) * ly * a;
            float w11 = lx * ly * a;

            int x1 = x0 + 1, y1 = y0 + 1;
            bool vx0 = (x0 >= 0) & (x0 < W);
            bool vx1 = (x1 >= 0) & (x1 < W);
            bool vy0 = (y0 >= 0) & (y0 < H);
            bool vy1 = (y1 >= 0) & (y1 < H);

            if (vy0 & vx0) acc += w00 * vch[(size_t)(S + y0 * W + x0) * CATN];
            if (vy0 & vx1) acc += w01 * vch[(size_t)(S + y0 * W + x1) * CATN];
            if (vy1 & vx0) acc += w10 * vch[(size_t)(S + y1 * W + x0) * CATN];
            if (vy1 & vx1) acc += w11 * vch[(size_t)(S + y1 * W + x1) * CATN];
        }
    }
    out[(size_t)bn * E_ + h * HDIM + lane] = to_tf32(acc);  // feeds Wo GEMM
}

// ---------------- fused residual add + LayerNorm (warp per row) ----------------
__global__ __launch_bounds__(256) void add_ln_kernel(
    const float* __restrict__ x, const float* __restrict__ r,
    const float* __restrict__ gamma, const float* __restrict__ beta,
    float* __restrict__ out, int M, int round_out)
{
    int row = blockIdx.x * 8 + (threadIdx.x >> 5);
    if (row >= M) return;
    int lane = threadIdx.x & 31;

    const float* xp = x + (size_t)row * E_;
    const float* rp = r + (size_t)row * E_;

    float vals[8];
    float s = 0.f;
    #pragma unroll
    for (int i = 0; i < 8; i++) {
        vals[i] = xp[lane + i * 32] + rp[lane + i * 32];
        s += vals[i];
    }
    #pragma unroll
    for (int o = 16; o > 0; o >>= 1) s += __shfl_xor_sync(0xFFFFFFFFu, s, o);
    float mean = s * (1.f / E_);

    float vs = 0.f;
    #pragma unroll
    for (int i = 0; i < 8; i++) {
        float d = vals[i] - mean;
        vs += d * d;
    }
    #pragma unroll
    for (int o = 16; o > 0; o >>= 1) vs += __shfl_xor_sync(0xFFFFFFFFu, vs, o);
    float inv = rsqrtf(vs * (1.f / E_) + EPS);

    float* op = out + (size_t)row * E_;
    #pragma unroll
    for (int i = 0; i < 8; i++) {
        int c = lane + i * 32;
        float v = (vals[i] - mean) * inv * gamma[c] + beta[c];
        op[c] = round_out ? to_tf32(v) : v;
    }
}

// ---------------- launcher ----------------
static inline void run_gemm(const float* A, const float* W, const float* b,
                            float* C, int M, int K, int Nc, int relu, int round_out) {
    dim3 grid(Nc / TBN, (M + TBM - 1) / TBM);
    gemm_tf32<<<grid, 256, GEMM_SMEM_BYTES>>>(A, W, b, C, M, K, Nc, relu, round_out);
}

extern "C" void kernel_launch(void* const* d_in, const int* in_sizes, int n_in,
                              void* d_out, int out_size) {
    const float* src  = (const float*)d_in[0];
    const float* ref  = (const float*)d_in[1];
    const float* Woff = (const float*)d_in[4];
    const float* boff = (const float*)d_in[5];
    const float* Waw  = (const float*)d_in[6];
    const float* baw  = (const float*)d_in[7];
    const float* Wv   = (const float*)d_in[8];
    const float* bv   = (const float*)d_in[9];
    const float* Wo   = (const float*)d_in[10];
    const float* bo   = (const float*)d_in[11];
    const float* ln1g = (const float*)d_in[12];
    const float* ln1b = (const float*)d_in[13];
    const float* Wf1  = (const float*)d_in[14];
    const float* bf1  = (const float*)d_in[15];
    const float* Wf2  = (const float*)d_in[16];
    const float* bf2  = (const float*)d_in[17];
    const float* ln2g = (const float*)d_in[18];
    const float* ln2b = (const float*)d_in[19];
    float* out = (float*)d_out;

    cudaFuncSetAttribute(gemm_tf32, cudaFuncAttributeMaxDynamicSharedMemorySize, GEMM_SMEM_BYTES);

    float *px, *pvoa, *psamp, *ptmp, *pffn, *pwcat, *pbcat, *pwo, *pwf1, *pwf2;
    cudaGetSymbolAddress((void**)&px,    g_x);
    cudaGetSymbolAddress((void**)&pvoa,  g_voa);
    cudaGetSymbolAddress((void**)&psamp, g_samp);
    cudaGetSymbolAddress((void**)&ptmp,  g_tmp);
    cudaGetSymbolAddress((void**)&pffn,  g_ffn);
    cudaGetSymbolAddress((void**)&pwcat, g_wcat);
    cudaGetSymbolAddress((void**)&pbcat, g_bcat);
    cudaGetSymbolAddress((void**)&pwo,   g_wo);
    cudaGetSymbolAddress((void**)&pwf1,  g_wf1);
    cudaGetSymbolAddress((void**)&pwf2,  g_wf2);

    const int M = MROWS;
    const int nElem = M * E_;

    // tf32-round input activation and all weights once
    round_copy_kernel<<<(nElem + 255) / 256, 256>>>(src, px, nElem);
    concat_w_kernel<<<(E_ * CATN + 255) / 256, 256>>>(Wv, Woff, Waw, bv, boff, baw, pwcat, pbcat);
    round_copy_kernel<<<(E_ * E_ + 255) / 256, 256>>>(Wo,  pwo,  E_ * E_);
    round_copy_kernel<<<(E_ * F_ + 255) / 256, 256>>>(Wf1, pwf1, E_ * F_);
    round_copy_kernel<<<(F_ * E_ + 255) / 256, 256>>>(Wf2, pwf2, F_ * E_);

    for (int layer = 0; layer < 6; layer++) {
        // fused projections: [v | off | aw-logits]
        run_gemm(px, pwcat, pbcat, pvoa, M, E_, CATN, 0, 0);

        deform_attn_kernel<<<M, 256>>>(pvoa, ref, psamp);

        run_gemm(psamp, pwo, bo, ptmp, M, E_, E_, 0, 0);
        add_ln_kernel<<<(M + 7) / 8, 256>>>(px, ptmp, ln1g, ln1b, px, M, 1);

        run_gemm(px,   pwf1, bf1, pffn, M, E_, F_, 1, 1);   // relu + round (feeds FFN2)
        run_gemm(pffn, pwf2, bf2, ptmp, M, F_, E_, 0, 0);

        float* dst = (layer == 5) ? out : px;
        add_ln_kernel<<<(M + 7) / 8, 256>>>(px, ptmp, ln2g, ln2b, dst, M, (layer == 5) ? 0 : 1);
    }
}

// round 5
// speedup vs baseline: 2.8913x; 1.1621x over previous
#include <cuda_runtime.h>
#include <cuda_fp16.h>
#include <math.h>
#include <stdint.h>

// ---------------- static problem config ----------------
#define NQ     13294
#define BATCH  2
#define MROWS  (BATCH * NQ)     // 26588
#define E_     256
#define F_     1024
#define CATN   640              // concat proj width: 256 (v) + 256 (off) + 128 (aw)
#define NHEAD  8
#define HDIM   32
#define NLVL   4
#define NPNT   4
#define EPS    1e-5f

// ---------------- scratch (static device globals; no allocation) ----------------
__device__ float  g_x   [MROWS * E_];    // fp32 residual stream
__device__ __half g_xh  [MROWS * E_];    // fp16 view for GEMM A
__device__ __half g_voa [MROWS * CATN];  // [v | off | aw-logits] fp16
__device__ __half g_samp[MROWS * E_];    // deform output (GEMM A)
__device__ float  g_tmp [MROWS * E_];    // fp32 branch output (pre-LN)
__device__ __half g_ffn [MROWS * F_];    // FFN hidden
__device__ __half g_wcat[E_ * CATN];
__device__ float  g_bcat[CATN];
__device__ __half g_wo  [E_ * E_];
__device__ __half g_wf1 [E_ * F_];
__device__ __half g_wf2 [F_ * E_];

__constant__ int c_w[NLVL]     = {100, 50, 25, 13};
__constant__ int c_h[NLVL]     = {100, 50, 25, 13};
__constant__ int c_start[NLVL] = {0, 10000, 12500, 13125};

// ---------------- utility ----------------
__global__ void src_copy_kernel(const float* __restrict__ src,
                                float* __restrict__ xf, __half* __restrict__ xh, int n) {
    int i = blockIdx.x * blockDim.x + threadIdx.x;
    if (i < n) { float v = src[i]; xf[i] = v; xh[i] = __float2half(v); }
}

__global__ void w2h_kernel(const float* __restrict__ src, __half* __restrict__ dst, int n) {
    int i = blockIdx.x * blockDim.x + threadIdx.x;
    if (i < n) dst[i] = __float2half(src[i]);
}

__global__ void concat_w_kernel(
    const float* __restrict__ Wv, const float* __restrict__ Woff, const float* __restrict__ Waw,
    const float* __restrict__ bv, const float* __restrict__ boff, const float* __restrict__ baw,
    __half* __restrict__ Wcat, float* __restrict__ bcat)
{
    int i = blockIdx.x * blockDim.x + threadIdx.x;
    if (i < E_ * CATN) {
        int r = i / CATN, c = i % CATN;
        float v;
        if (c < 256)      v = Wv  [r * 256 + c];
        else if (c < 512) v = Woff[r * 256 + (c - 256)];
        else              v = Waw [r * 128 + (c - 512)];
        Wcat[i] = __float2half(v);
    }
    if (i < CATN) {
        bcat[i] = (i < 256) ? bv[i] : (i < 512) ? boff[i - 256] : baw[i - 512];
    }
}

// ---------------- cp.async helpers ----------------
__device__ __forceinline__ void cp_async16(void* smem_dst, const void* gmem_src, bool pred) {
    uint32_t saddr = (uint32_t)__cvta_generic_to_shared(smem_dst);
    int sz = pred ? 16 : 0;
    asm volatile("cp.async.cg.shared.global [%0], [%1], 16, %2;\n"
                 :: "r"(saddr), "l"(gmem_src), "r"(sz));
}
#define CP_COMMIT() asm volatile("cp.async.commit_group;\n" ::: "memory")
#define CP_WAIT1()  asm volatile("cp.async.wait_group 1;\n" ::: "memory")

// ---------------- FP16 tensor-core GEMM ----------------
// C = act(A[MxK]h * W[KxN]h + bias_f), fp32 accum. 128x128x32 CTA tile,
// 256 threads (8 warps 2x4), warp 64x32 via 4x4 mma.m16n8k16,
// 3-stage cp.async pipeline, ldmatrix fragment loads.
#define TBM 128
#define TBN 128
#define TBK 32
#define APADH 40    // As row stride (halves): 80B -> conflict-free ldmatrix
#define BPADH 136   // Bs row stride (halves): 272B
#define NSTAGE 3
#define AS_STAGE (TBM * APADH)        // 5120 halves
#define BS_STAGE (TBK * BPADH)        // 4352 halves
#define GEMM_SMEM_BYTES ((NSTAGE * (AS_STAGE + BS_STAGE)) * 2)   // 56832

__device__ __forceinline__ void mma_f16(
    float& d0, float& d1, float& d2, float& d3,
    uint32_t a0, uint32_t a1, uint32_t a2, uint32_t a3,
    uint32_t b0, uint32_t b1)
{
    asm volatile(
        "mma.sync.aligned.m16n8k16.row.col.f32.f16.f16.f32 "
        "{%0,%1,%2,%3}, {%4,%5,%6,%7}, {%8,%9}, {%0,%1,%2,%3};"
        : "+f"(d0), "+f"(d1), "+f"(d2), "+f"(d3)
        : "r"(a0), "r"(a1), "r"(a2), "r"(a3), "r"(b0), "r"(b1));
}

__device__ __forceinline__ void ldsm_x4(uint32_t& r0, uint32_t& r1, uint32_t& r2, uint32_t& r3,
                                        const __half* p) {
    uint32_t addr = (uint32_t)__cvta_generic_to_shared(p);
    asm volatile("ldmatrix.sync.aligned.m8n8.x4.shared.b16 {%0,%1,%2,%3}, [%4];"
                 : "=r"(r0), "=r"(r1), "=r"(r2), "=r"(r3) : "r"(addr));
}

__device__ __forceinline__ void ldsm_x2_trans(uint32_t& r0, uint32_t& r1, const __half* p) {
    uint32_t addr = (uint32_t)__cvta_generic_to_shared(p);
    asm volatile("ldmatrix.sync.aligned.m8n8.x2.trans.shared.b16 {%0,%1}, [%2];"
                 : "=r"(r0), "=r"(r1) : "r"(addr));
}

__global__ __launch_bounds__(256, 2) void gemm_f16(
    const __half* __restrict__ A, const __half* __restrict__ W,
    const float* __restrict__ bias, void* __restrict__ Cout,
    int M, int K, int N, int relu, int out_half)
{
    extern __shared__ __half sm[];
    __half* Asm = sm;                          // NSTAGE * AS_STAGE
    __half* Bsm = sm + NSTAGE * AS_STAGE;      // NSTAGE * BS_STAGE

    const int tid = threadIdx.x;
    const int bm  = blockIdx.y * TBM;
    const int bn  = blockIdx.x * TBN;

    // A tile loads: 128 rows x 32 halves (64B/row, 4 x 16B). 2 rows/thread.
    const int row_a = tid >> 2;            // 0..63 (and +64)
    const int col_a = (tid & 3) << 3;      // 0,8,16,24 halves
    // B tile loads: 32 rows x 128 halves (256B/row, 16 x 16B). 2 rows/thread.
    const int row_b = tid >> 4;            // 0..15 (and +16)
    const int col_b = (tid & 15) << 3;     // 0..120 halves

    const bool a0_ok = (bm + row_a)      < M;
    const bool a1_ok = (bm + row_a + 64) < M;

    const int w    = tid >> 5;
    const int wm   = (w & 1) * 64;
    const int wn   = (w >> 1) * 32;
    const int lane = tid & 31;
    const int gid  = lane >> 2;
    const int tig  = lane & 3;
    const int l16  = lane & 15;
    const int lhi  = (lane >> 4) << 3;     // 0 or 8

    float acc[4][4][4] = {};

    const int KT = K >> 5;   // 32-wide k tiles

    const __half* Abase0 = A + (size_t)(bm + row_a)      * K + col_a;
    const __half* Abase1 = A + (size_t)(bm + row_a + 64) * K + col_a;
    const __half* Bbase0 = W + (size_t)row_b        * N + bn + col_b;
    const __half* Bbase1 = W + (size_t)(row_b + 16) * N + bn + col_b;

    __half* asm_dst0[NSTAGE];
    __half* asm_dst1[NSTAGE];
    __half* bsm_dst0[NSTAGE];
    __half* bsm_dst1[NSTAGE];
    #pragma unroll
    for (int s = 0; s < NSTAGE; s++) {
        asm_dst0[s] = Asm + s * AS_STAGE + row_a * APADH + col_a;
        asm_dst1[s] = Asm + s * AS_STAGE + (row_a + 64) * APADH + col_a;
        bsm_dst0[s] = Bsm + s * BS_STAGE + row_b * BPADH + col_b;
        bsm_dst1[s] = Bsm + s * BS_STAGE + (row_b + 16) * BPADH + col_b;
    }

    // prologue: stages 0..NSTAGE-2
    #pragma unroll
    for (int s = 0; s < NSTAGE - 1; s++) {
        const int k0 = s << 5;
        cp_async16(asm_dst0[s], Abase0 + k0, a0_ok);
        cp_async16(asm_dst1[s], Abase1 + k0, a1_ok);
        cp_async16(bsm_dst0[s], Bbase0 + (size_t)k0 * N, true);
        cp_async16(bsm_dst1[s], Bbase1 + (size_t)k0 * N, true);
        CP_COMMIT();
    }

    for (int kt = 0; kt < KT; kt++) {
        CP_WAIT1();
        __syncthreads();

        if (kt + NSTAGE - 1 < KT) {
            const int s  = (kt + NSTAGE - 1) % NSTAGE;
            const int k0 = (kt + NSTAGE - 1) << 5;
            cp_async16(asm_dst0[s], Abase0 + k0, a0_ok);
            cp_async16(asm_dst1[s], Abase1 + k0, a1_ok);
            cp_async16(bsm_dst0[s], Bbase0 + (size_t)k0 * N, true);
            cp_async16(bsm_dst1[s], Bbase1 + (size_t)k0 * N, true);
        }
        CP_COMMIT();

        const __half* Ab = Asm + (kt % NSTAGE) * AS_STAGE;
        const __half* Bb = Bsm + (kt % NSTAGE) * BS_STAGE;

        #pragma unroll
        for (int ks = 0; ks < 2; ks++) {            // two k16 steps
            const int kk = ks << 4;
            uint32_t af[4][4];
            uint32_t bf[4][2];
            #pragma unroll
            for (int mt = 0; mt < 4; mt++) {
                const int r0 = wm + mt * 16;
                ldsm_x4(af[mt][0], af[mt][1], af[mt][2], af[mt][3],
                        Ab + (size_t)(r0 + l16) * APADH + kk + lhi);
            }
            #pragma unroll
            for (int nt = 0; nt < 4; nt++) {
                ldsm_x2_trans(bf[nt][0], bf[nt][1],
                              Bb + (size_t)(kk + l16) * BPADH + wn + nt * 8);
            }
            #pragma unroll
            for (int mt = 0; mt < 4; mt++)
                #pragma unroll
                for (int nt = 0; nt < 4; nt++)
                    mma_f16(acc[mt][nt][0], acc[mt][nt][1], acc[mt][nt][2], acc[mt][nt][3],
                            af[mt][0], af[mt][1], af[mt][2], af[mt][3],
                            bf[nt][0], bf[nt][1]);
        }
    }

    // epilogue: bias (+relu), float2 or half2 stores
    float*  Cf = (float*)Cout;
    __half* Ch = (__half*)Cout;
    #pragma unroll
    for (int mt = 0; mt < 4; mt++) {
        const int r0 = bm + wm + mt * 16 + gid;
        const int r1 = r0 + 8;
        #pragma unroll
        for (int nt = 0; nt < 4; nt++) {
            const int c = bn + wn + nt * 8 + tig * 2;
            const float b0 = bias[c], b1 = bias[c + 1];
            float v0 = acc[mt][nt][0] + b0;
            float v1 = acc[mt][nt][1] + b1;
            float v2 = acc[mt][nt][2] + b0;
            float v3 = acc[mt][nt][3] + b1;
            if (relu) {
                v0 = fmaxf(v0, 0.f); v1 = fmaxf(v1, 0.f);
                v2 = fmaxf(v2, 0.f); v3 = fmaxf(v3, 0.f);
            }
            if (out_half) {
                if (r0 < M) *(__half2*)(Ch + (size_t)r0 * N + c) = __floats2half2_rn(v0, v1);
                if (r1 < M) *(__half2*)(Ch + (size_t)r1 * N + c) = __floats2half2_rn(v2, v3);
            } else {
                if (r0 < M) *(float2*)(Cf + (size_t)r0 * N + c) = make_float2(v0, v1);
                if (r1 < M) *(float2*)(Cf + (size_t)r1 * N + c) = make_float2(v2, v3);
            }
        }
    }
}

// ---------------- multi-scale deformable attention (softmax fused, fp16 data) ----------------
__global__ __launch_bounds__(256) void deform_attn_kernel(
    const __half* __restrict__ voa, const float* __restrict__ ref,
    __half* __restrict__ out)
{
    int gw = blockIdx.x * 8 + (threadIdx.x >> 5);
    if (gw >= MROWS * NHEAD) return;
    int lane = threadIdx.x & 31;
    int h  = gw & 7;
    int bn = gw >> 3;
    int b  = bn / NQ;
    const size_t vb = (size_t)b * NQ;

    const __half* offp = voa + (size_t)bn * CATN + 256 + h * 32;  // (L,P,2)
    const __half* awp  = voa + (size_t)bn * CATN + 512 + h * 16;  // (L,P) logits

    // inline softmax over 16 logits
    float logit = __half2float(awp[lane & 15]);
    float mx = logit;
    #pragma unroll
    for (int o = 8; o > 0; o >>= 1) mx = fmaxf(mx, __shfl_xor_sync(0xFFFFFFFFu, mx, o));
    float e = __expf(logit - mx);
    float ssum = e;
    #pragma unroll
    for (int o = 8; o > 0; o >>= 1) ssum += __shfl_xor_sync(0xFFFFFFFFu, ssum, o);
    float prob = e / ssum;

    const __half* vch = voa + vb * CATN + h * HDIM + lane;

    float acc = 0.f;

    #pragma unroll
    for (int lvl = 0; lvl < NLVL; lvl++) {
        const int W = c_w[lvl], H = c_h[lvl], S = c_start[lvl];
        const float fw = (float)W, fh = (float)H;
        float rx = ref[((size_t)bn * NLVL + lvl) * 2 + 0];
        float ry = ref[((size_t)bn * NLVL + lvl) * 2 + 1];

        #pragma unroll
        for (int p = 0; p < NPNT; p++) {
            float ox = __half2float(offp[(lvl * NPNT + p) * 2 + 0]);
            float oy = __half2float(offp[(lvl * NPNT + p) * 2 + 1]);
            float a  = __shfl_sync(0xFFFFFFFFu, prob, lvl * NPNT + p, 16);

            float locx = rx + ox / fw;
            float locy = ry + oy / fh;
            float xs = locx * fw - 0.5f;
            float ys = locy * fh - 0.5f;

            float fxs = floorf(xs), fys = floorf(ys);
            int x0 = (int)fxs, y0 = (int)fys;
            float lx = xs - fxs, ly = ys - fys;

            float w00 = (1.f - lx) * (1.f - ly) * a;
            float w01 = lx * (1.f - ly) * a;
            float w10 = (1.f - lx) * ly * a;
            float w11 = lx * ly * a;

            int x1 = x0 + 1, y1 = y0 + 1;
            bool vx0 = (x0 >= 0) & (x0 < W);
            bool vx1 = (x1 >= 0) & (x1 < W);
            bool vy0 = (y0 >= 0) & (y0 < H);
            bool vy1 = (y1 >= 0) & (y1 < H);

            if (vy0 & vx0) acc += w00 * __half2float(vch[(size_t)(S + y0 * W + x0) * CATN]);
            if (vy0 & vx1) acc += w01 * __half2float(vch[(size_t)(S + y0 * W + x1) * CATN]);
            if (vy1 & vx0) acc += w10 * __half2float(vch[(size_t)(S + y1 * W + x0) * CATN]);
            if (vy1 & vx1) acc += w11 * __half2float(vch[(size_t)(S + y1 * W + x1) * CATN]);
        }
    }
    out[(size_t)bn * E_ + h * HDIM + lane] = __float2half(acc);
}

// ---------------- fused residual add + LayerNorm (warp per row) ----------------
// residual stream stays fp32 (out_f); GEMM-input view written fp16 (out_h, optional)
__global__ __launch_bounds__(256) void add_ln_kernel(
    const float* __restrict__ x, const float* __restrict__ r,
    const float* __restrict__ gamma, const float* __restrict__ beta,
    float* __restrict__ out_f, __half* __restrict__ out_h, int M)
{
    int row = blockIdx.x * 8 + (threadIdx.x >> 5);
    if (row >= M) return;
    int lane = threadIdx.x & 31;

    const float* xp = x + (size_t)row * E_;
    const float* rp = r + (size_t)row * E_;

    float vals[8];
    float s = 0.f;
    #pragma unroll
    for (int i = 0; i < 8; i++) {
        vals[i] = xp[lane + i * 32] + rp[lane + i * 32];
        s += vals[i];
    }
    #pragma unroll
    for (int o = 16; o > 0; o >>= 1) s += __shfl_xor_sync(0xFFFFFFFFu, s, o);
    float mean = s * (1.f / E_);

    float vs = 0.f;
    #pragma unroll
    for (int i = 0; i < 8; i++) {
        float d = vals[i] - mean;
        vs += d * d;
    }
    #pragma unroll
    for (int o = 16; o > 0; o >>= 1) vs += __shfl_xor_sync(0xFFFFFFFFu, vs, o);
    float inv = rsqrtf(vs * (1.f / E_) + EPS);

    float*  opf = out_f + (size_t)row * E_;
    #pragma unroll
    for (int i = 0; i < 8; i++) {
        int c = lane + i * 32;
        float v = (vals[i] - mean) * inv * gamma[c] + beta[c];
        opf[c] = v;
        if (out_h) out_h[(size_t)row * E_ + c] = __float2half(v);
    }
}

// ---------------- launcher ----------------
static inline void run_gemm(const __half* A, const __half* W, const float* b,
                            void* C, int M, int K, int Nc, int relu, int out_half) {
    dim3 grid(Nc / TBN, (M + TBM - 1) / TBM);
    gemm_f16<<<grid, 256, GEMM_SMEM_BYTES>>>(A, W, b, C, M, K, Nc, relu, out_half);
}

extern "C" void kernel_launch(void* const* d_in, const int* in_sizes, int n_in,
                              void* d_out, int out_size) {
    const float* src  = (const float*)d_in[0];
    const float* ref  = (const float*)d_in[1];
    const float* Woff = (const float*)d_in[4];
    const float* boff = (const float*)d_in[5];
    const float* Waw  = (const float*)d_in[6];
    const float* baw  = (const float*)d_in[7];
    const float* Wv   = (const float*)d_in[8];
    const float* bv   = (const float*)d_in[9];
    const float* Wo   = (const float*)d_in[10];
    const float* bo   = (const float*)d_in[11];
    const float* ln1g = (const float*)d_in[12];
    const float* ln1b = (const float*)d_in[13];
    const float* Wf1  = (const float*)d_in[14];
    const float* bf1  = (const float*)d_in[15];
    const float* Wf2  = (const float*)d_in[16];
    const float* bf2  = (const float*)d_in[17];
    const float* ln2g = (const float*)d_in[18];
    const float* ln2b = (const float*)d_in[19];
    float* out = (float*)d_out;

    cudaFuncSetAttribute(gemm_f16, cudaFuncAttributeMaxDynamicSharedMemorySize, GEMM_SMEM_BYTES);

    float *px, *ptmp, *pbcat;
    __half *pxh, *pvoa, *psamp, *pffn, *pwcat, *pwo, *pwf1, *pwf2;
    cudaGetSymbolAddress((void**)&px,    g_x);
    cudaGetSymbolAddress((void**)&pxh,   g_xh);
    cudaGetSymbolAddress((void**)&pvoa,  g_voa);
    cudaGetSymbolAddress((void**)&psamp, g_samp);
    cudaGetSymbolAddress((void**)&ptmp,  g_tmp);
    cudaGetSymbolAddress((void**)&pffn,  g_ffn);
    cudaGetSymbolAddress((void**)&pwcat, g_wcat);
    cudaGetSymbolAddress((void**)&pbcat, g_bcat);
    cudaGetSymbolAddress((void**)&pwo,   g_wo);
    cudaGetSymbolAddress((void**)&pwf1,  g_wf1);
    cudaGetSymbolAddress((void**)&pwf2,  g_wf2);

    const int M = MROWS;
    const int nElem = M * E_;

    src_copy_kernel<<<(nElem + 255) / 256, 256>>>(src, px, pxh, nElem);
    concat_w_kernel<<<(E_ * CATN + 255) / 256, 256>>>(Wv, Woff, Waw, bv, boff, baw, pwcat, pbcat);
    w2h_kernel<<<(E_ * E_ + 255) / 256, 256>>>(Wo,  pwo,  E_ * E_);
    w2h_kernel<<<(E_ * F_ + 255) / 256, 256>>>(Wf1, pwf1, E_ * F_);
    w2h_kernel<<<(F_ * E_ + 255) / 256, 256>>>(Wf2, pwf2, F_ * E_);

    for (int layer = 0; layer < 6; layer++) {
        // fused projections: [v | off | aw-logits], fp16 out
        run_gemm(pxh, pwcat, pbcat, pvoa, M, E_, CATN, 0, 1);

        deform_attn_kernel<<<M, 256>>>(pvoa, ref, psamp);

        run_gemm(psamp, pwo, bo, ptmp, M, E_, E_, 0, 0);                 // fp32 out
        add_ln_kernel<<<(M + 7) / 8, 256>>>(px, ptmp, ln1g, ln1b, px, pxh, M);

        run_gemm(pxh,  pwf1, bf1, pffn, M, E_, F_, 1, 1);                // relu, fp16 out
        run_gemm(pffn, pwf2, bf2, ptmp, M, F_, E_, 0, 0);                // fp32 out

        float* dst = (layer == 5) ? out : px;
        __half* dsth = (layer == 5) ? (__half*)nullptr : pxh;
        add_ln_kernel<<<(M + 7) / 8, 256>>>(px, ptmp, ln2g, ln2b, dst, dsth, M);
    }
}

// round 7
// speedup vs baseline: 2.8982x; 1.0024x over previous
#include <cuda_runtime.h>
#include <cuda_fp16.h>
#include <math.h>
#include <stdint.h>

// ---------------- static problem config ----------------
#define NQ     13294
#define BATCH  2
#define MROWS  (BATCH * NQ)     // 26588
#define E_     256
#define F_     1024
#define CATN   640              // concat proj width: 256 (v) + 256 (off) + 128 (aw)
#define NHEAD  8
#define HDIM   32
#define NLVL   4
#define NPNT   4
#define EPS    1e-5f

// ---------------- scratch (static device globals; no allocation) ----------------
__device__ float  g_x   [MROWS * E_];    // fp32 residual stream
__device__ __half g_xh  [MROWS * E_];    // fp16 view for GEMM A
__device__ __half g_voa [MROWS * CATN];  // [v | off | aw-logits] fp16
__device__ __half g_samp[MROWS * E_];    // deform output (GEMM A)
__device__ float  g_tmp [MROWS * E_];    // fp32 branch output (pre-LN)
__device__ __half g_ffn [MROWS * F_];    // FFN hidden
__device__ __half g_wcat[E_ * CATN];
__device__ float  g_bcat[CATN];
__device__ __half g_wo  [E_ * E_];
__device__ __half g_wf1 [E_ * F_];
__device__ __half g_wf2 [F_ * E_];

__constant__ int c_w[NLVL]     = {100, 50, 25, 13};
__constant__ int c_h[NLVL]     = {100, 50, 25, 13};
__constant__ int c_start[NLVL] = {0, 10000, 12500, 13125};

// ---------------- prep kernels ----------------
__global__ void src_copy_kernel(const float* __restrict__ src,
                                float* __restrict__ xf, __half* __restrict__ xh, int n) {
    int i = blockIdx.x * blockDim.x + threadIdx.x;
    if (i < n) { float v = src[i]; xf[i] = v; xh[i] = __float2half(v); }
}

__global__ void w2h_kernel(const float* __restrict__ src, __half* __restrict__ dst, int n) {
    int i = blockIdx.x * blockDim.x + threadIdx.x;
    if (i < n) dst[i] = __float2half(src[i]);
}

__global__ void concat_w_kernel(
    const float* __restrict__ Wv, const float* __restrict__ Woff, const float* __restrict__ Waw,
    const float* __restrict__ bv, const float* __restrict__ boff, const float* __restrict__ baw,
    __half* __restrict__ Wcat, float* __restrict__ bcat)
{
    int i = blockIdx.x * blockDim.x + threadIdx.x;
    if (i < E_ * CATN) {
        int r = i / CATN, c = i % CATN;
        float v;
        if (c < 256)      v = Wv  [r * 256 + c];
        else if (c < 512) v = Woff[r * 256 + (c - 256)];
        else              v = Waw [r * 128 + (c - 512)];
        Wcat[i] = __float2half(v);
    }
    if (i < CATN) {
        bcat[i] = (i < 256) ? bv[i] : (i < 512) ? boff[i - 256] : baw[i - 512];
    }
}

// ---------------- cp.async helpers ----------------
__device__ __forceinline__ void cp_async16(void* smem_dst, const void* gmem_src, bool pred) {
    uint32_t saddr = (uint32_t)__cvta_generic_to_shared(smem_dst);
    int sz = pred ? 16 : 0;
    asm volatile("cp.async.cg.shared.global [%0], [%1], 16, %2;\n"
                 :: "r"(saddr), "l"(gmem_src), "r"(sz));
}
#define CP_COMMIT() asm volatile("cp.async.commit_group;\n" ::: "memory")
#define CP_WAIT1()  asm volatile("cp.async.wait_group 1;\n" ::: "memory")

// ---------------- FP16 tensor-core GEMM ----------------
// C = act(A[MxK]h * W[KxN]h + bias_f), fp32 accum. 128x128x64 CTA tile,
// 256 threads (8 warps 2x4), warp 64x32 via 4x4 mma.m16n8k16,
// 3-stage cp.async pipeline, ldmatrix x4 (A) / x4.trans (B) fragment loads.
#define TBM 128
#define TBN 128
#define TBK 64
#define APADH 72    // As row stride (halves): 144B, 16B-aligned
#define BPADH 136   // Bs row stride (halves): 272B
#define NSTAGE 3
#define AS_STAGE (TBM * APADH)        // 9216 halves
#define BS_STAGE (TBK * BPADH)        // 8704 halves
#define GEMM_SMEM_BYTES ((NSTAGE * (AS_STAGE + BS_STAGE)) * 2)   // 107520

__device__ __forceinline__ void mma_f16(
    float& d0, float& d1, float& d2, float& d3,
    uint32_t a0, uint32_t a1, uint32_t a2, uint32_t a3,
    uint32_t b0, uint32_t b1)
{
    asm volatile(
        "mma.sync.aligned.m16n8k16.row.col.f32.f16.f16.f32 "
        "{%0,%1,%2,%3}, {%4,%5,%6,%7}, {%8,%9}, {%0,%1,%2,%3};"
        : "+f"(d0), "+f"(d1), "+f"(d2), "+f"(d3)
        : "r"(a0), "r"(a1), "r"(a2), "r"(a3), "r"(b0), "r"(b1));
}

__device__ __forceinline__ void ldsm_x4(uint32_t& r0, uint32_t& r1, uint32_t& r2, uint32_t& r3,
                                        const __half* p) {
    uint32_t addr = (uint32_t)__cvta_generic_to_shared(p);
    asm volatile("ldmatrix.sync.aligned.m8n8.x4.shared.b16 {%0,%1,%2,%3}, [%4];"
                 : "=r"(r0), "=r"(r1), "=r"(r2), "=r"(r3) : "r"(addr));
}

__device__ __forceinline__ void ldsm_x4_trans(uint32_t& r0, uint32_t& r1, uint32_t& r2, uint32_t& r3,
                                              const __half* p) {
    uint32_t addr = (uint32_t)__cvta_generic_to_shared(p);
    asm volatile("ldmatrix.sync.aligned.m8n8.x4.trans.shared.b16 {%0,%1,%2,%3}, [%4];"
                 : "=r"(r0), "=r"(r1), "=r"(r2), "=r"(r3) : "r"(addr));
}

__global__ __launch_bounds__(256, 2) void gemm_f16(
    const __half* __restrict__ A, const __half* __restrict__ W,
    const float* __restrict__ bias, void* __restrict__ Cout,
    int M, int K, int N, int relu, int out_half)
{
    extern __shared__ __half sm[];
    __half* Asm = sm;                          // NSTAGE * AS_STAGE
    __half* Bsm = sm + NSTAGE * AS_STAGE;      // NSTAGE * BS_STAGE

    const int tid = threadIdx.x;
    const int bm  = blockIdx.y * TBM;
    const int bn  = blockIdx.x * TBN;

    // A tile: 128 rows x 64 halves (128B/row). 2 threads/row, 4 x 16B each.
    const int row_a = tid >> 1;            // 0..127
    const int col_a = (tid & 1) << 5;      // 0 or 32 halves (64B)
    // B tile: 64 rows x 128 halves (256B/row). 4 threads/row, 4 x 16B each.
    const int row_b = tid >> 2;            // 0..63
    const int col_b = (tid & 3) << 5;      // 0,32,64,96 halves

    const bool a_ok = (bm + row_a) < M;

    const int w    = tid >> 5;
    const int wm   = (w & 1) * 64;
    const int wn   = (w >> 1) * 32;
    const int lane = tid & 31;
    const int gid  = lane >> 2;
    const int tig  = lane & 3;
    const int l16  = lane & 15;
    const int lhi  = (lane >> 4) << 3;     // 0 or 8

    float acc[4][4][4] = {};

    const int KT = K >> 6;   // 64-wide k tiles

    const __half* Abase = A + (size_t)(bm + row_a) * K + col_a;
    const __half* Bbase = W + (size_t)row_b * N + bn + col_b;

    __half* asm_dst[NSTAGE];
    __half* bsm_dst[NSTAGE];
    #pragma unroll
    for (int s = 0; s < NSTAGE; s++) {
        asm_dst[s] = Asm + s * AS_STAGE + row_a * APADH + col_a;
        bsm_dst[s] = Bsm + s * BS_STAGE + row_b * BPADH + col_b;
    }

    // prologue: issue stages 0..NSTAGE-2
    #pragma unroll
    for (int s = 0; s < NSTAGE - 1; s++) {
        const int k0 = s << 6;
        #pragma unroll
        for (int i = 0; i < 4; i++) {
            cp_async16(asm_dst[s] + i * 8, Abase + k0 + i * 8, a_ok);
            cp_async16(bsm_dst[s] + i * 8, Bbase + (size_t)k0 * N + i * 8, true);
        }
        CP_COMMIT();
    }

    for (int kt = 0; kt < KT; kt++) {
        CP_WAIT1();
        __syncthreads();

        if (kt + NSTAGE - 1 < KT) {
            const int s  = (kt + NSTAGE - 1) % NSTAGE;
            const int k0 = (kt + NSTAGE - 1) << 6;
            #pragma unroll
            for (int i = 0; i < 4; i++) {
                cp_async16(asm_dst[s] + i * 8, Abase + k0 + i * 8, a_ok);
                cp_async16(bsm_dst[s] + i * 8, Bbase + (size_t)k0 * N + i * 8, true);
            }
        }
        CP_COMMIT();

        const __half* Ab = Asm + (kt % NSTAGE) * AS_STAGE;
        const __half* Bb = Bsm + (kt % NSTAGE) * BS_STAGE;

        #pragma unroll
        for (int ks = 0; ks < 4; ks++) {            // four k16 steps
            const int kk = ks << 4;
            uint32_t af[4][4];
            uint32_t bf[4][2];
            #pragma unroll
            for (int mt = 0; mt < 4; mt++) {
                const int r0 = wm + mt * 16;
                ldsm_x4(af[mt][0], af[mt][1], af[mt][2], af[mt][3],
                        Ab + (size_t)(r0 + l16) * APADH + kk + lhi);
            }
            #pragma unroll
            for (int pr = 0; pr < 2; pr++) {        // each x4.trans covers two nt tiles
                const int c0 = wn + pr * 16;
                ldsm_x4_trans(bf[pr * 2][0], bf[pr * 2][1], bf[pr * 2 + 1][0], bf[pr * 2 + 1][1],
                              Bb + (size_t)(kk + l16) * BPADH + c0 + lhi);
            }
            #pragma unroll
            for (int mt = 0; mt < 4; mt++)
                #pragma unroll
                for (int nt = 0; nt < 4; nt++)
                    mma_f16(acc[mt][nt][0], acc[mt][nt][1], acc[mt][nt][2], acc[mt][nt][3],
                            af[mt][0], af[mt][1], af[mt][2], af[mt][3],
                            bf[nt][0], bf[nt][1]);
        }
    }

    // epilogue: bias (+relu), float2 or half2 stores
    float*  Cf = (float*)Cout;
    __half* Ch = (__half*)Cout;
    #pragma unroll
    for (int mt = 0; mt < 4; mt++) {
        const int r0 = bm + wm + mt * 16 + gid;
        const int r1 = r0 + 8;
        #pragma unroll
        for (int nt = 0; nt < 4; nt++) {
            const int c = bn + wn + nt * 8 + tig * 2;
            const float b0 = bias[c], b1 = bias[c + 1];
            float v0 = acc[mt][nt][0] + b0;
            float v1 = acc[mt][nt][1] + b1;
            float v2 = acc[mt][nt][2] + b0;
            float v3 = acc[mt][nt][3] + b1;
            if (relu) {
                v0 = fmaxf(v0, 0.f); v1 = fmaxf(v1, 0.f);
                v2 = fmaxf(v2, 0.f); v3 = fmaxf(v3, 0.f);
            }
            if (out_half) {
                if (r0 < M) *(__half2*)(Ch + (size_t)r0 * N + c) = __floats2half2_rn(v0, v1);
                if (r1 < M) *(__half2*)(Ch + (size_t)r1 * N + c) = __floats2half2_rn(v2, v3);
            } else {
                if (r0 < M) *(float2*)(Cf + (size_t)r0 * N + c) = make_float2(v0, v1);
                if (r1 < M) *(float2*)(Cf + (size_t)r1 * N + c) = make_float2(v2, v3);
            }
        }
    }
}

// ---------------- multi-scale deformable attention (softmax fused, fp16 data) ----------------
__global__ __launch_bounds__(256) void deform_attn_kernel(
    const __half* __restrict__ voa, const float* __restrict__ ref,
    __half* __restrict__ out)
{
    int gw = blockIdx.x * 8 + (threadIdx.x >> 5);
    if (gw >= MROWS * NHEAD) return;
    int lane = threadIdx.x & 31;
    int h  = gw & 7;
    int bn = gw >> 3;
    int b  = bn / NQ;
    const size_t vb = (size_t)b * NQ;

    const __half* offp = voa + (size_t)bn * CATN + 256 + h * 32;
    const __half* awp  = voa + (size_t)bn * CATN + 512 + h * 16;

    float logit = __half2float(awp[lane & 15]);
    float mx = logit;
    #pragma unroll
    for (int o = 8; o > 0; o >>= 1) mx = fmaxf(mx, __shfl_xor_sync(0xFFFFFFFFu, mx, o));
    float e = __expf(logit - mx);
    float ssum = e;
    #pragma unroll
    for (int o = 8; o > 0; o >>= 1) ssum += __shfl_xor_sync(0xFFFFFFFFu, ssum, o);
    float prob = e / ssum;

    const __half* vch = voa + vb * CATN + h * HDIM + lane;

    float acc = 0.f;

    #pragma unroll
    for (int lvl = 0; lvl < NLVL; lvl++) {
        const int W = c_w[lvl], H = c_h[lvl], S = c_start[lvl];
        const float fw = (float)W, fh = (float)H;
        float rx = ref[((size_t)bn * NLVL + lvl) * 2 + 0];
        float ry = ref[((size_t)bn * NLVL + lvl) * 2 + 1];

        #pragma unroll
        for (int p = 0; p < NPNT; p++) {
            float ox = __half2float(offp[(lvl * NPNT + p) * 2 + 0]);
            float oy = __half2float(offp[(lvl * NPNT + p) * 2 + 1]);
            float a  = __shfl_sync(0xFFFFFFFFu, prob, lvl * NPNT + p, 16);

            float locx = rx + ox / fw;
            float locy = ry + oy / fh;
            float xs = locx * fw - 0.5f;
            float ys = locy * fh - 0.5f;

            float fxs = floorf(xs), fys = floorf(ys);
            int x0 = (int)fxs, y0 = (int)fys;
            float lx = xs - fxs, ly = ys - fys;

            float w00 = (1.f - lx) * (1.f - ly) * a;
            float w01 = lx * (1.f - ly) * a;
            float w10 = (1.f - lx) * ly * a;
            float w11 = lx * ly * a;

            int x1 = x0 + 1, y1 = y0 + 1;
            bool vx0 = (x0 >= 0) & (x0 < W);
            bool vx1 = (x1 >= 0) & (x1 < W);
            bool vy0 = (y0 >= 0) & (y0 < H);
            bool vy1 = (y1 >= 0) & (y1 < H);

            if (vy0 & vx0) acc += w00 * __half2float(vch[(size_t)(S + y0 * W + x0) * CATN]);
            if (vy0 & vx1) acc += w01 * __half2float(vch[(size_t)(S + y0 * W + x1) * CATN]);
            if (vy1 & vx0) acc += w10 * __half2float(vch[(size_t)(S + y1 * W + x0) * CATN]);
            if (vy1 & vx1) acc += w11 * __half2float(vch[(size_t)(S + y1 * W + x1) * CATN]);
        }
    }
    out[(size_t)bn * E_ + h * HDIM + lane] = __float2half(acc);
}

// ---------------- fused residual add + LayerNorm (warp per row) ----------------
__global__ __launch_bounds__(256) void add_ln_kernel(
    const float* __restrict__ x, const float* __restrict__ r,
    const float* __restrict__ gamma, const float* __restrict__ beta,
    float* __restrict__ out_f, __half* __restrict__ out_h, int M)
{
    int row = blockIdx.x * 8 + (threadIdx.x >> 5);
    if (row >= M) return;
    int lane = threadIdx.x & 31;

    const float* xp = x + (size_t)row * E_;
    const float* rp = r + (size_t)row * E_;

    float vals[8];
    float s = 0.f;
    #pragma unroll
    for (int i = 0; i < 8; i++) {
        vals[i] = xp[lane + i * 32] + rp[lane + i * 32];
        s += vals[i];
    }
    #pragma unroll
    for (int o = 16; o > 0; o >>= 1) s += __shfl_xor_sync(0xFFFFFFFFu, s, o);
    float mean = s * (1.f / E_);

    float vs = 0.f;
    #pragma unroll
    for (int i = 0; i < 8; i++) {
        float d = vals[i] - mean;
        vs += d * d;
    }
    #pragma unroll
    for (int o = 16; o > 0; o >>= 1) vs += __shfl_xor_sync(0xFFFFFFFFu, vs, o);
    float inv = rsqrtf(vs * (1.f / E_) + EPS);

    float* opf = out_f + (size_t)row * E_;
    #pragma unroll
    for (int i = 0; i < 8; i++) {
        int c = lane + i * 32;
        float v = (vals[i] - mean) * inv * gamma[c] + beta[c];
        opf[c] = v;
        if (out_h) out_h[(size_t)row * E_ + c] = __float2half(v);
    }
}

// ---------------- launcher ----------------
static inline void run_gemm(const __half* A, const __half* W, const float* b,
                            void* C, int M, int K, int Nc, int relu, int out_half) {
    dim3 grid(Nc / TBN, (M + TBM - 1) / TBM);
    gemm_f16<<<grid, 256, GEMM_SMEM_BYTES>>>(A, W, b, C, M, K, Nc, relu, out_half);
}

extern "C" void kernel_launch(void* const* d_in, const int* in_sizes, int n_in,
                              void* d_out, int out_size) {
    const float* src  = (const float*)d_in[0];
    const float* ref  = (const float*)d_in[1];
    const float* Woff = (const float*)d_in[4];
    const float* boff = (const float*)d_in[5];
    const float* Waw  = (const float*)d_in[6];
    const float* baw  = (const float*)d_in[7];
    const float* Wv   = (const float*)d_in[8];
    const float* bv   = (const float*)d_in[9];
    const float* Wo   = (const float*)d_in[10];
    const float* bo   = (const float*)d_in[11];
    const float* ln1g = (const float*)d_in[12];
    const float* ln1b = (const float*)d_in[13];
    const float* Wf1  = (const float*)d_in[14];
    const float* bf1  = (const float*)d_in[15];
    const float* Wf2  = (const float*)d_in[16];
    const float* bf2  = (const float*)d_in[17];
    const float* ln2g = (const float*)d_in[18];
    const float* ln2b = (const float*)d_in[19];
    float* out = (float*)d_out;

    cudaFuncSetAttribute(gemm_f16, cudaFuncAttributeMaxDynamicSharedMemorySize, GEMM_SMEM_BYTES);

    float *px, *ptmp, *pbcat;
    __half *pxh, *pvoa, *psamp, *pffn, *pwcat, *pwo, *pwf1, *pwf2;
    cudaGetSymbolAddress((void**)&px,    g_x);
    cudaGetSymbolAddress((void**)&pxh,   g_xh);
    cudaGetSymbolAddress((void**)&pvoa,  g_voa);
    cudaGetSymbolAddress((void**)&psamp, g_samp);
    cudaGetSymbolAddress((void**)&ptmp,  g_tmp);
    cudaGetSymbolAddress((void**)&pffn,  g_ffn);
    cudaGetSymbolAddress((void**)&pwcat, g_wcat);
    cudaGetSymbolAddress((void**)&pbcat, g_bcat);
    cudaGetSymbolAddress((void**)&pwo,   g_wo);
    cudaGetSymbolAddress((void**)&pwf1,  g_wf1);
    cudaGetSymbolAddress((void**)&pwf2,  g_wf2);

    const int M = MROWS;
    const int nElem = M * E_;

    src_copy_kernel<<<(nElem + 255) / 256, 256>>>(src, px, pxh, nElem);
    concat_w_kernel<<<(E_ * CATN + 255) / 256, 256>>>(Wv, Woff, Waw, bv, boff, baw, pwcat, pbcat);
    w2h_kernel<<<(E_ * E_ + 255) / 256, 256>>>(Wo,  pwo,  E_ * E_);
    w2h_kernel<<<(E_ * F_ + 255) / 256, 256>>>(Wf1, pwf1, E_ * F_);
    w2h_kernel<<<(F_ * E_ + 255) / 256, 256>>>(Wf2, pwf2, F_ * E_);

    for (int layer = 0; layer < 6; layer++) {
        // fused projections: [v | off | aw-logits], fp16 out
        run_gemm(pxh, pwcat, pbcat, pvoa, M, E_, CATN, 0, 1);

        deform_attn_kernel<<<M, 256>>>(pvoa, ref, psamp);

        run_gemm(psamp, pwo, bo, ptmp, M, E_, E_, 0, 0);                 // fp32 out
        add_ln_kernel<<<(M + 7) / 8, 256>>>(px, ptmp, ln1g, ln1b, px, pxh, M);

        run_gemm(pxh,  pwf1, bf1, pffn, M, E_, F_, 1, 1);                // relu, fp16 out
        run_gemm(pffn, pwf2, bf2, ptmp, M, F_, E_, 0, 0);                // fp32 out

        float* dst = (layer == 5) ? out : px;
        __half* dsth = (layer == 5) ? (__half*)nullptr : pxh;
        add_ln_kernel<<<(M + 7) / 8, 256>>>(px, ptmp, ln2g, ln2b, dst, dsth, M);
    }
}